// round 6
// baseline (speedup 1.0000x reference)
#include <cuda_runtime.h>
#include <cuda_bf16.h>
#include <cstdint>

#define BATCH 64
#define HDIM  1024
#define LSEQ  2048
#define NVOC  32000
#define G3    3072
#define ACH   64    // attention L-rows per CTA

// ---------------- scratch (device globals; no allocation) ----------------
__device__ __nv_bfloat16 g_xhi[BATCH*HDIM],  g_xlo[BATCH*HDIM];
__device__ __nv_bfloat16 g_hphi[2*BATCH*HDIM], g_hplo[2*BATCH*HDIM];
__device__ __nv_bfloat16 g_h0hi[BATCH*HDIM], g_h0lo[BATCH*HDIM];
__device__ float         g_gpart[8*BATCH*G3];     // [y*4+z][64][3072]
__device__ float         g_h1[BATCH*HDIM];
__device__ __nv_bfloat16 g_cathi[BATCH*2*HDIM], g_catlo[BATCH*2*HDIM];
__device__ float         g_scores[BATCH*LSEQ];
__device__ float         g_pm[BATCH*32], g_ps[BATCH*32];
__device__ float         g_pctx[BATCH*32*HDIM];   // 8MB
__device__ float         g_ccpart[16*BATCH*HDIM]; // [z][64][1024]
__device__ __nv_bfloat16 g_cchi[BATCH*HDIM], g_cclo[BATCH*HDIM];
__device__ float         g_wpart[2*BATCH*NVOC];   // Wout split-K partials

// ---------------- helpers ----------------
__device__ __forceinline__ uint32_t pk_hi(float x, float y){
    return (__float_as_uint(x) >> 16) | (__float_as_uint(y) & 0xffff0000u);
}
__device__ __forceinline__ uint32_t pk_lo(float x, float y){
    float rx = x - __uint_as_float(__float_as_uint(x) & 0xffff0000u);
    float ry = y - __uint_as_float(__float_as_uint(y) & 0xffff0000u);
    return (__float_as_uint(rx) >> 16) | (__float_as_uint(ry) & 0xffff0000u);
}
__device__ __forceinline__ void split1(float v, __nv_bfloat16* hi, __nv_bfloat16* lo){
    uint32_t u  = __float_as_uint(v);
    uint32_t uh = u & 0xffff0000u;
    float r = v - __uint_as_float(uh);
    *hi = __ushort_as_bfloat16((unsigned short)(uh >> 16));
    *lo = __ushort_as_bfloat16((unsigned short)(__float_as_uint(r) >> 16));
}
__device__ __forceinline__ void mma16816(float* c, const uint32_t* a, uint32_t b0, uint32_t b1){
    asm volatile("mma.sync.aligned.m16n8k16.row.col.f32.bf16.bf16.f32 "
        "{%0,%1,%2,%3}, {%4,%5,%6,%7}, {%8,%9}, {%0,%1,%2,%3};"
        : "+f"(c[0]), "+f"(c[1]), "+f"(c[2]), "+f"(c[3])
        : "r"(a[0]), "r"(a[1]), "r"(a[2]), "r"(a[3]), "r"(b0), "r"(b1));
}
__device__ __forceinline__ void cp16(void* sdst, const void* gsrc){
    uint32_t s = (uint32_t)__cvta_generic_to_shared(sdst);
    asm volatile("cp.async.cg.shared.global [%0], [%1], 16;" :: "r"(s), "l"(gsrc));
}

// ---------------- prep: embed gather + hi/lo split of x and h_prev ----------------
__global__ void prep_k(const int* __restrict__ seq, const float* __restrict__ embed,
                       const float* __restrict__ lh)
{
    int idx = blockIdx.x*256 + threadIdx.x;     // 3 * 65536
    int z = idx >> 16, r = idx & 65535;
    float v;
    if (z == 0){
        int b = r >> 10, j = r & 1023;
        v = embed[(size_t)seq[b]*HDIM + j];
    } else {
        v = lh[(size_t)(z-1)*BATCH*HDIM + r];
    }
    __nv_bfloat16 hi, lo; split1(v, &hi, &lo);
    if (z == 0){ g_xhi[r] = hi; g_xlo[r] = lo; }
    else       { g_hphi[(z-1)*BATCH*HDIM + r] = hi; g_hplo[(z-1)*BATCH*HDIM + r] = lo; }
}

// ---------------- split-precision GEMM: 3-stage cp.async pipeline, stride-40 W ----------------
// partial = act(64xK) @ W(NxK)^T for K-range [zz*KS, (zz+1)*KS)
// mode 0/1: GRU layer 0/1 -> g_gpart   mode 2: Wc -> g_ccpart   mode 3: Wout -> g_wpart
#define GSMEM 92160
__global__ void __launch_bounds__(256, 2)
gemm2_k(const float* __restrict__ W0, const float* __restrict__ W1,
        float* __restrict__ dummy,
        int K, int N, int KS, int mode)
{
    extern __shared__ char sraw[];
    float*    sW  = (float*)sraw;                  // [3][128][40] fp32
    uint32_t* sAh = (uint32_t*)(sraw + 61440);     // [3][64][20]
    uint32_t* sAl = (uint32_t*)(sraw + 76800);     // [3][64][20]

    int y = blockIdx.y, zz = blockIdx.z;
    const float* W = y ? W1 : W0;
    const __nv_bfloat16 *Ahp, *Alp;
    float* op;
    if (mode == 0){ Ahp = y ? g_hphi : g_xhi;  Alp = y ? g_hplo : g_xlo;  op = g_gpart; }
    else if (mode == 1){
        Ahp = y ? (g_hphi + BATCH*HDIM) : g_h0hi;
        Alp = y ? (g_hplo + BATCH*HDIM) : g_h0lo;  op = g_gpart;
    } else if (mode == 2){ Ahp = g_cathi; Alp = g_catlo; op = g_ccpart; }
    else { Ahp = g_cchi;  Alp = g_cclo;  op = g_wpart; }
    const uint32_t* Agh = (const uint32_t*)Ahp;
    const uint32_t* Agl = (const uint32_t*)Alp;

    int tid = threadIdx.x, w = tid >> 5, lane = tid & 31;
    int r = lane >> 2, c = lane & 3;
    int nblk = blockIdx.x * 128;
    int K2 = K >> 1;
    int kbeg = zz * KS;
    int nch = KS >> 5;

    auto load_chunk = [&](int ch, int buf){
        int ck = kbeg + ch*32;
        const float* Wg = W + (size_t)nblk*K + ck;
        float* wd = sW + buf*5120;
        #pragma unroll
        for (int i = 0; i < 4; i++){
            int p = tid + i*256;
            int row = p >> 3, c4 = p & 7;
            cp16(wd + row*40 + c4*4, Wg + (size_t)row*K + c4*4);
        }
        int row = tid >> 2, c4 = tid & 3;
        const uint32_t* ah = Agh + (ck>>1) + (size_t)row*K2 + c4*4;
        const uint32_t* al = Agl + (ck>>1) + (size_t)row*K2 + c4*4;
        cp16(sAh + buf*1280 + row*20 + c4*4, ah);
        cp16(sAl + buf*1280 + row*20 + c4*4, al);
    };

    float acc[4][2][4];
    #pragma unroll
    for (int i=0;i<4;i++)
        #pragma unroll
        for (int j=0;j<2;j++)
            #pragma unroll
            for (int q=0;q<4;q++) acc[i][j][q] = 0.f;

    load_chunk(0, 0);
    asm volatile("cp.async.commit_group;");
    load_chunk(1, 1);
    asm volatile("cp.async.commit_group;");

    for (int ch = 0; ch < nch; ch++){
        int buf = ch % 3;
        __syncthreads();
        if (ch + 2 < nch){
            load_chunk(ch+2, (ch+2) % 3);
            asm volatile("cp.async.commit_group;");
            asm volatile("cp.async.wait_group 2;");
        } else if (ch + 1 < nch){
            asm volatile("cp.async.wait_group 1;");
        } else {
            asm volatile("cp.async.wait_group 0;");
        }
        __syncthreads();

        const float2* wb = (const float2*)(sW + buf*5120);
        const uint32_t* ab = sAh + buf*1280;
        const uint32_t* al = sAl + buf*1280;

        #pragma unroll
        for (int ki = 0; ki < 2; ki++){
            uint32_t bh[2][2], bl[2][2];
            #pragma unroll
            for (int nt = 0; nt < 2; nt++){
                int nl = w*16 + nt*8 + r;
                const float2* wp = wb + nl*20 + ki*8 + c;
                float2 w0 = wp[0], w1 = wp[4];
                bh[nt][0] = pk_hi(w0.x, w0.y);  bl[nt][0] = pk_lo(w0.x, w0.y);
                bh[nt][1] = pk_hi(w1.x, w1.y);  bl[nt][1] = pk_lo(w1.x, w1.y);
            }
            int kl = ki*8 + c;
            #pragma unroll
            for (int mt = 0; mt < 4; mt++){
                int rowa = mt*16 + r;
                uint32_t ah[4], aw[4];
                ah[0] = ab[rowa*20 + kl];        aw[0] = al[rowa*20 + kl];
                ah[1] = ab[(rowa+8)*20 + kl];    aw[1] = al[(rowa+8)*20 + kl];
                ah[2] = ab[rowa*20 + kl + 4];    aw[2] = al[rowa*20 + kl + 4];
                ah[3] = ab[(rowa+8)*20 + kl+4];  aw[3] = al[(rowa+8)*20 + kl + 4];
                #pragma unroll
                for (int nt = 0; nt < 2; nt++){
                    mma16816(acc[mt][nt], ah, bh[nt][0], bh[nt][1]);
                    mma16816(acc[mt][nt], aw, bh[nt][0], bh[nt][1]);
                    mma16816(acc[mt][nt], ah, bl[nt][0], bl[nt][1]);
                }
            }
        }
    }

    int nw = nblk + w*16, cq = c*2;
    float* o = op + (size_t)((y*gridDim.z + zz) * 64) * N;
    #pragma unroll
    for (int mt = 0; mt < 4; mt++)
        #pragma unroll
        for (int nt = 0; nt < 2; nt++){
            int row = mt*16 + r, col = nw + nt*8 + cq;
            *(float2*)(o + (size_t)row*N + col)     = make_float2(acc[mt][nt][0], acc[mt][nt][1]);
            *(float2*)(o + (size_t)(row+8)*N + col) = make_float2(acc[mt][nt][2], acc[mt][nt][3]);
        }
}

// ---------------- GRU elementwise cell (4 split-K partials) ----------------
__global__ void gru_cell_k(const float* __restrict__ bi, const float* __restrict__ bh,
                           const float* __restrict__ hprev, float* __restrict__ hout,
                           int layer)
{
    int idx = blockIdx.x*256 + threadIdx.x;   // 65536
    int b = idx >> 10, j = idx & 1023;
    float xr=0.f, xz=0.f, xn=0.f, hr=0.f, hz=0.f, hn=0.f;
    #pragma unroll
    for (int ks = 0; ks < 4; ks++){
        const float* gi = g_gpart + (size_t)(ks*64 + b)*G3;
        const float* gh = g_gpart + (size_t)((4+ks)*64 + b)*G3;
        xr += gi[j]; xz += gi[1024+j]; xn += gi[2048+j];
        hr += gh[j]; hz += gh[1024+j]; hn += gh[2048+j];
    }
    xr += bi[j]; xz += bi[1024+j]; xn += bi[2048+j];
    hr += bh[j]; hz += bh[1024+j]; hn += bh[2048+j];
    float rr = 1.f/(1.f + expf(-(xr+hr)));
    float zg = 1.f/(1.f + expf(-(xz+hz)));
    float nn = tanhf(xn + rr*hn);
    float h  = (1.f - zg)*nn + zg*hprev[idx];
    hout[idx] = h;
    __nv_bfloat16 hi, lo; split1(h, &hi, &lo);
    if (layer == 0){ g_h0hi[idx] = hi; g_h0lo[idx] = lo; }
    else { g_cathi[b*2048 + j] = hi; g_catlo[b*2048 + j] = lo; g_h1[idx] = h; }
}

// ---------------- attention pass 1: branchless online softmax, depth-2 reg prefetch ----------------
__global__ void __launch_bounds__(128, 3) attn_pass_k(const float* __restrict__ enc)
{
    __shared__ float4 shv[256];        // h1 for this batch row
    __shared__ float4 cbuf4[4][256];
    __shared__ float sm_m[4], sm_s[4];

    int b = blockIdx.y, cch = blockIdx.x;
    int tid = threadIdx.x, w = tid >> 5, lane = tid & 31;

    for (int i = tid; i < 256; i += 128) shv[i] = ((const float4*)g_h1)[b*256 + i];
    __syncthreads();

    float4 ctx[8];
    #pragma unroll
    for (int k = 0; k < 8; k++) ctx[k] = make_float4(0.f,0.f,0.f,0.f);
    float m = -1e30f, ssum = 0.f;

    const float4* ebase = (const float4*)(enc + ((size_t)b*LSEQ + cch*ACH + w*16)*1024);
    uint32_t hvad = (uint32_t)__cvta_generic_to_shared(&shv[lane]);

    float4 buf0[8], buf1[8], buf2[8];
    #pragma unroll
    for (int k = 0; k < 8; k++) buf0[k] = ebase[lane + 32*k];
    #pragma unroll
    for (int k = 0; k < 8; k++) buf1[k] = ebase[256 + lane + 32*k];

    #pragma unroll
    for (int i = 0; i < 16; i++){
        float4* cur = (i%3==0) ? buf0 : ((i%3==1) ? buf1 : buf2);
        float4* nxt = ((i+2)%3==0) ? buf0 : (((i+2)%3==1) ? buf1 : buf2);
        if (i + 2 < 16){
            const float4* src = ebase + (size_t)(i+2)*256;
            #pragma unroll
            for (int k = 0; k < 8; k++) nxt[k] = src[lane + 32*k];
        }
        float d0=0.f, d1=0.f, d2=0.f, d3=0.f;
        #pragma unroll
        for (int k = 0; k < 8; k++){
            float4 hvk;
            asm volatile("ld.shared.v4.f32 {%0,%1,%2,%3}, [%4];"
                : "=f"(hvk.x), "=f"(hvk.y), "=f"(hvk.z), "=f"(hvk.w)
                : "r"(hvad + (uint32_t)(k*512)));
            d0 = fmaf(cur[k].x, hvk.x, d0);
            d1 = fmaf(cur[k].y, hvk.y, d1);
            d2 = fmaf(cur[k].z, hvk.z, d2);
            d3 = fmaf(cur[k].w, hvk.w, d3);
        }
        float d = (d0 + d1) + (d2 + d3);
        #pragma unroll
        for (int off = 16; off; off >>= 1) d += __shfl_xor_sync(0xffffffffu, d, off);
        if (lane == 0) g_scores[b*LSEQ + cch*ACH + w*16 + i] = d;
        float mn = fmaxf(m, d);
        float sc = __expf(m - mn);
        float wg = __expf(d - mn);
        ssum = ssum * sc + wg;
        m = mn;
        #pragma unroll
        for (int k = 0; k < 8; k++){
            ctx[k].x = fmaf(ctx[k].x, sc, wg*cur[k].x);
            ctx[k].y = fmaf(ctx[k].y, sc, wg*cur[k].y);
            ctx[k].z = fmaf(ctx[k].z, sc, wg*cur[k].z);
            ctx[k].w = fmaf(ctx[k].w, sc, wg*cur[k].w);
        }
    }

    if (lane == 0){ sm_m[w] = m; sm_s[w] = ssum; }
    __syncthreads();
    float mb = fmaxf(fmaxf(sm_m[0], sm_m[1]), fmaxf(sm_m[2], sm_m[3]));
    float sce = __expf(m - mb);
    #pragma unroll
    for (int k = 0; k < 8; k++)
        cbuf4[w][lane + 32*k] = make_float4(ctx[k].x*sce, ctx[k].y*sce, ctx[k].z*sce, ctx[k].w*sce);
    __syncthreads();
    const float* cb = (const float*)cbuf4;
    for (int e = tid; e < 1024; e += 128){
        float s = cb[e] + cb[1024 + e] + cb[2048 + e] + cb[3072 + e];
        g_pctx[(size_t)(b*32 + cch)*1024 + e] = s;
    }
    if (tid == 0){
        float zb = 0.f;
        #pragma unroll
        for (int jw = 0; jw < 4; jw++) zb += sm_s[jw]*__expf(sm_m[jw] - mb);
        g_pm[b*32 + cch] = mb; g_ps[b*32 + cch] = zb;
    }
}

// ---------------- attention finalize ----------------
__global__ void attn_fin_k(float* __restrict__ out_attn)
{
    __shared__ float we[32];
    int b = blockIdx.x, tid = threadIdx.x;
    float M = -1e30f;
    #pragma unroll
    for (int cc = 0; cc < 32; cc++) M = fmaxf(M, g_pm[b*32 + cc]);
    float Z = 0.f;
    #pragma unroll
    for (int cc = 0; cc < 32; cc++) Z += g_ps[b*32 + cc]*__expf(g_pm[b*32 + cc] - M);
    float inv = 1.f / Z;
    if (tid < 32) we[tid] = __expf(g_pm[b*32 + tid] - M);
    __syncthreads();
    for (int l = tid; l < LSEQ; l += 256)
        out_attn[b*LSEQ + l] = __expf(g_scores[b*LSEQ + l] - M) * inv;
    for (int e = tid; e < 1024; e += 256){
        float s = 0.f;
        #pragma unroll
        for (int cc = 0; cc < 32; cc++)
            s += we[cc] * g_pctx[(size_t)(b*32 + cc)*1024 + e];
        float v = s * inv;
        __nv_bfloat16 hi, lo; split1(v, &hi, &lo);
        g_cathi[b*2048 + 1024 + e] = hi; g_catlo[b*2048 + 1024 + e] = lo;
    }
}

// ---------------- Wc combine ----------------
__global__ void cc_comb_k(const float* __restrict__ bc)
{
    int idx = blockIdx.x*256 + threadIdx.x;  // 65536
    int b = idx >> 10, n = idx & 1023;
    float s = bc[n];
    #pragma unroll
    for (int z = 0; z < 16; z++) s += g_ccpart[(size_t)(z*64 + b)*1024 + n];
    float v = tanhf(s);
    __nv_bfloat16 hi, lo; split1(v, &hi, &lo);
    g_cchi[idx] = hi; g_cclo[idx] = lo;
}

// ---------------- Wout combine: partials + bias ----------------
__global__ void wout_comb_k(const float* __restrict__ bout, float* __restrict__ out)
{
    int i4 = blockIdx.x*256 + threadIdx.x;   // float4 index, 64*32000/4 = 512000
    int b = i4 / 8000, n = i4 - b*8000;
    const float4* p0 = (const float4*)g_wpart;
    const float4* p1 = (const float4*)(g_wpart + (size_t)BATCH*NVOC);
    float4 a = p0[i4], cpt = p1[i4], bb = ((const float4*)bout)[n];
    (void)b;
    ((float4*)out)[i4] = make_float4(a.x + cpt.x + bb.x, a.y + cpt.y + bb.y,
                                     a.z + cpt.z + bb.z, a.w + cpt.w + bb.w);
}

// ---------------- launch ----------------
extern "C" void kernel_launch(void* const* d_in, const int* in_sizes, int n_in,
                              void* d_out, int out_size)
{
    const int*   seq  = (const int*)d_in[0];
    const float* lh   = (const float*)d_in[1];
    const float* enc  = (const float*)d_in[2];
    const float* emb  = (const float*)d_in[3];
    const float* Wih0 = (const float*)d_in[4];
    const float* Whh0 = (const float*)d_in[5];
    const float* bih0 = (const float*)d_in[6];
    const float* bhh0 = (const float*)d_in[7];
    const float* Wih1 = (const float*)d_in[8];
    const float* Whh1 = (const float*)d_in[9];
    const float* bih1 = (const float*)d_in[10];
    const float* bhh1 = (const float*)d_in[11];
    const float* Wc   = (const float*)d_in[12];
    const float* bc   = (const float*)d_in[13];
    const float* Wout = (const float*)d_in[14];
    const float* bout = (const float*)d_in[15];

    float* out        = (float*)d_out;
    float* out_logits = out;                                   // [64, 32000]
    float* out_hidden = out + (size_t)BATCH*NVOC;              // [2, 64, 1024]
    float* out_attn   = out_hidden + 2*BATCH*HDIM;             // [64, 1, 2048]

    cudaFuncSetAttribute(gemm2_k, cudaFuncAttributeMaxDynamicSharedMemorySize, GSMEM);

    prep_k<<<768, 256>>>(seq, emb, lh);

    gemm2_k<<<dim3(24, 2, 4), 256, GSMEM>>>(Wih0, Whh0, nullptr, 1024, G3, 256, 0);
    gru_cell_k<<<256, 256>>>(bih0, bhh0, lh, out_hidden, 0);

    gemm2_k<<<dim3(24, 2, 4), 256, GSMEM>>>(Wih1, Whh1, nullptr, 1024, G3, 256, 1);
    gru_cell_k<<<256, 256>>>(bih1, bhh1, lh + BATCH*HDIM, out_hidden + BATCH*HDIM, 1);

    attn_pass_k<<<dim3(32, 64), 128>>>(enc);
    attn_fin_k<<<64, 256>>>(out_attn);

    gemm2_k<<<dim3(8, 1, 16), 256, GSMEM>>>(Wc, nullptr, nullptr, 2048, 1024, 128, 2);
    cc_comb_k<<<256, 256>>>(bc);

    gemm2_k<<<dim3(250, 1, 2), 256, GSMEM>>>(Wout, nullptr, nullptr, 1024, NVOC, 512, 3);
    wout_comb_k<<<2000, 256>>>(bout, out_logits);
}

// round 7
// speedup vs baseline: 1.0112x; 1.0112x over previous
#include <cuda_runtime.h>
#include <cuda_bf16.h>
#include <cstdint>

#define BATCH 64
#define HDIM  1024
#define LSEQ  2048
#define NVOC  32000
#define G3    3072
#define ACH   64    // attention L-rows per CTA

// ---------------- scratch (device globals; no allocation) ----------------
__device__ __nv_bfloat16 g_xhi[BATCH*HDIM],  g_xlo[BATCH*HDIM];
__device__ __nv_bfloat16 g_hphi[2*BATCH*HDIM], g_hplo[2*BATCH*HDIM];
__device__ __nv_bfloat16 g_h0hi[BATCH*HDIM], g_h0lo[BATCH*HDIM];
__device__ float         g_gpart[8*BATCH*G3];     // [y*4+z][64][3072]
__device__ float         g_h1[BATCH*HDIM];
__device__ __nv_bfloat16 g_cathi[BATCH*2*HDIM], g_catlo[BATCH*2*HDIM];
__device__ float         g_scores[BATCH*LSEQ];
__device__ float         g_pm[BATCH*32], g_ps[BATCH*32];
__device__ float         g_pctx[BATCH*32*HDIM];   // 8MB
__device__ float         g_ccpart[16*BATCH*HDIM]; // [z][64][1024]
__device__ __nv_bfloat16 g_cchi[BATCH*HDIM], g_cclo[BATCH*HDIM];

// ---------------- helpers ----------------
__device__ __forceinline__ uint32_t pk_hi(float x, float y){
    return (__float_as_uint(x) >> 16) | (__float_as_uint(y) & 0xffff0000u);
}
__device__ __forceinline__ uint32_t pk_lo(float x, float y){
    float rx = x - __uint_as_float(__float_as_uint(x) & 0xffff0000u);
    float ry = y - __uint_as_float(__float_as_uint(y) & 0xffff0000u);
    return (__float_as_uint(rx) >> 16) | (__float_as_uint(ry) & 0xffff0000u);
}
__device__ __forceinline__ void split1(float v, __nv_bfloat16* hi, __nv_bfloat16* lo){
    uint32_t u  = __float_as_uint(v);
    uint32_t uh = u & 0xffff0000u;
    float r = v - __uint_as_float(uh);
    *hi = __ushort_as_bfloat16((unsigned short)(uh >> 16));
    *lo = __ushort_as_bfloat16((unsigned short)(__float_as_uint(r) >> 16));
}
__device__ __forceinline__ void mma16816(float* c, const uint32_t* a, uint32_t b0, uint32_t b1){
    asm volatile("mma.sync.aligned.m16n8k16.row.col.f32.bf16.bf16.f32 "
        "{%0,%1,%2,%3}, {%4,%5,%6,%7}, {%8,%9}, {%0,%1,%2,%3};"
        : "+f"(c[0]), "+f"(c[1]), "+f"(c[2]), "+f"(c[3])
        : "r"(a[0]), "r"(a[1]), "r"(a[2]), "r"(a[3]), "r"(b0), "r"(b1));
}
__device__ __forceinline__ void ldsm4(uint32_t* d, uint32_t saddr){
    asm volatile("ldmatrix.sync.aligned.m8n8.x4.shared.b16 {%0,%1,%2,%3}, [%4];"
        : "=r"(d[0]), "=r"(d[1]), "=r"(d[2]), "=r"(d[3]) : "r"(saddr));
}
__device__ __forceinline__ void cp16(void* sdst, const void* gsrc){
    uint32_t s = (uint32_t)__cvta_generic_to_shared(sdst);
    asm volatile("cp.async.cg.shared.global [%0], [%1], 16;" :: "r"(s), "l"(gsrc));
}

// ---------------- prep: embed gather + hi/lo split of x and h_prev ----------------
__global__ void prep_k(const int* __restrict__ seq, const float* __restrict__ embed,
                       const float* __restrict__ lh)
{
    int idx = blockIdx.x*256 + threadIdx.x;     // 3 * 65536
    int z = idx >> 16, r = idx & 65535;
    float v;
    if (z == 0){
        int b = r >> 10, j = r & 1023;
        v = embed[(size_t)seq[b]*HDIM + j];
    } else {
        v = lh[(size_t)(z-1)*BATCH*HDIM + r];
    }
    __nv_bfloat16 hi, lo; split1(v, &hi, &lo);
    if (z == 0){ g_xhi[r] = hi; g_xlo[r] = lo; }
    else       { g_hphi[(z-1)*BATCH*HDIM + r] = hi; g_hplo[(z-1)*BATCH*HDIM + r] = lo; }
}

// ---------------- split-precision GEMM: 3-stage cp.async pipeline + ldmatrix A ----------------
// out = act(64xK) @ W(NxK)^T over K-range [zz*KS, (zz+1)*KS)
// mode 0/1: GRU layer 0/1 -> g_gpart   mode 2: Wc -> g_ccpart   mode 3: Wout+bias -> out_ext
#define GSMEM 92160
__global__ void __launch_bounds__(256, 2)
gemm2_k(const float* __restrict__ W0, const float* __restrict__ W1,
        const float* __restrict__ bias, float* __restrict__ out_ext,
        int K, int N, int KS, int mode)
{
    extern __shared__ char sraw[];
    float*    sW  = (float*)sraw;                  // [3][128][40] fp32
    uint32_t* sAh = (uint32_t*)(sraw + 61440);     // [3][64][20]
    uint32_t* sAl = (uint32_t*)(sraw + 76800);     // [3][64][20]

    int y = blockIdx.y, zz = blockIdx.z;
    const float* W = y ? W1 : W0;
    const __nv_bfloat16 *Ahp, *Alp;
    float* op;
    if (mode == 0){ Ahp = y ? g_hphi : g_xhi;  Alp = y ? g_hplo : g_xlo;  op = g_gpart; }
    else if (mode == 1){
        Ahp = y ? (g_hphi + BATCH*HDIM) : g_h0hi;
        Alp = y ? (g_hplo + BATCH*HDIM) : g_h0lo;  op = g_gpart;
    } else if (mode == 2){ Ahp = g_cathi; Alp = g_catlo; op = g_ccpart; }
    else { Ahp = g_cchi;  Alp = g_cclo;  op = out_ext; }
    const uint32_t* Agh = (const uint32_t*)Ahp;
    const uint32_t* Agl = (const uint32_t*)Alp;

    int tid = threadIdx.x, w = tid >> 5, lane = tid & 31;
    int r = lane >> 2, c = lane & 3;
    int nblk = blockIdx.x * 128;
    int K2 = K >> 1;
    int kbeg = zz * KS;
    int nch = KS >> 5;

    uint32_t smem_u = (uint32_t)__cvta_generic_to_shared(sraw);
    uint32_t aH = smem_u + 61440;
    uint32_t aL = smem_u + 76800;
    // ldmatrix per-lane address offset: lanes 0-15 -> rows 0-15 (col 0),
    // lanes 16-31 -> rows 0-15 (col +16B). Row stride 80B (40 bf16).
    uint32_t aoff = (uint32_t)((lane & 15)*80 + (lane >> 4)*16);

    auto load_chunk = [&](int ch, int buf){
        int ck = kbeg + ch*32;
        const float* Wg = W + (size_t)nblk*K + ck;
        float* wd = sW + buf*5120;
        #pragma unroll
        for (int i = 0; i < 4; i++){
            int p = tid + i*256;
            int row = p >> 3, c4 = p & 7;
            cp16(wd + row*40 + c4*4, Wg + (size_t)row*K + c4*4);
        }
        int row = tid >> 2, c4 = tid & 3;
        const uint32_t* ah = Agh + (ck>>1) + (size_t)row*K2 + c4*4;
        const uint32_t* al = Agl + (ck>>1) + (size_t)row*K2 + c4*4;
        cp16(sAh + buf*1280 + row*20 + c4*4, ah);
        cp16(sAl + buf*1280 + row*20 + c4*4, al);
    };

    float acc[4][2][4];
    #pragma unroll
    for (int i=0;i<4;i++)
        #pragma unroll
        for (int j=0;j<2;j++)
            #pragma unroll
            for (int q=0;q<4;q++) acc[i][j][q] = 0.f;

    load_chunk(0, 0);
    asm volatile("cp.async.commit_group;");
    load_chunk(1, 1);
    asm volatile("cp.async.commit_group;");

    for (int ch = 0; ch < nch; ch++){
        int buf = ch % 3;
        __syncthreads();
        if (ch + 2 < nch){
            load_chunk(ch+2, (ch+2) % 3);
            asm volatile("cp.async.commit_group;");
            asm volatile("cp.async.wait_group 2;");
        } else if (ch + 1 < nch){
            asm volatile("cp.async.wait_group 1;");
        } else {
            asm volatile("cp.async.wait_group 0;");
        }
        __syncthreads();

        const float2* wb = (const float2*)(sW + buf*5120);
        uint32_t aHb = aH + buf*5120 + aoff;
        uint32_t aLb = aL + buf*5120 + aoff;

        #pragma unroll
        for (int ki = 0; ki < 2; ki++){
            uint32_t bh[2][2], bl[2][2];
            #pragma unroll
            for (int nt = 0; nt < 2; nt++){
                int nl = w*16 + nt*8 + r;
                const float2* wp = wb + nl*20 + ki*8 + c;
                float2 w0 = wp[0], w1 = wp[4];
                bh[nt][0] = pk_hi(w0.x, w0.y);  bl[nt][0] = pk_lo(w0.x, w0.y);
                bh[nt][1] = pk_hi(w1.x, w1.y);  bl[nt][1] = pk_lo(w1.x, w1.y);
            }
            #pragma unroll
            for (int mt = 0; mt < 4; mt++){
                uint32_t ah[4], aw[4];
                ldsm4(ah, aHb + mt*1280 + ki*32);
                ldsm4(aw, aLb + mt*1280 + ki*32);
                #pragma unroll
                for (int nt = 0; nt < 2; nt++){
                    mma16816(acc[mt][nt], ah, bh[nt][0], bh[nt][1]);
                    mma16816(acc[mt][nt], aw, bh[nt][0], bh[nt][1]);
                    mma16816(acc[mt][nt], ah, bl[nt][0], bl[nt][1]);
                }
            }
        }
    }

    int nw = nblk + w*16, cq = c*2;
    if (mode < 3){
        float* o = op + (size_t)((y*gridDim.z + zz) * 64) * N;
        #pragma unroll
        for (int mt = 0; mt < 4; mt++)
            #pragma unroll
            for (int nt = 0; nt < 2; nt++){
                int row = mt*16 + r, col = nw + nt*8 + cq;
                *(float2*)(o + (size_t)row*N + col)     = make_float2(acc[mt][nt][0], acc[mt][nt][1]);
                *(float2*)(o + (size_t)(row+8)*N + col) = make_float2(acc[mt][nt][2], acc[mt][nt][3]);
            }
    } else {
        #pragma unroll
        for (int mt = 0; mt < 4; mt++)
            #pragma unroll
            for (int nt = 0; nt < 2; nt++){
                int row = mt*16 + r, col = nw + nt*8 + cq;
                float2 bb = *(const float2*)(bias + col);
                *(float2*)(out_ext + (size_t)row*N + col)     = make_float2(acc[mt][nt][0] + bb.x, acc[mt][nt][1] + bb.y);
                *(float2*)(out_ext + (size_t)(row+8)*N + col) = make_float2(acc[mt][nt][2] + bb.x, acc[mt][nt][3] + bb.y);
            }
    }
}

// ---------------- GRU elementwise cell (4 split-K partials) ----------------
__global__ void gru_cell_k(const float* __restrict__ bi, const float* __restrict__ bh,
                           const float* __restrict__ hprev, float* __restrict__ hout,
                           int layer)
{
    int idx = blockIdx.x*256 + threadIdx.x;   // 65536
    int b = idx >> 10, j = idx & 1023;
    float xr=0.f, xz=0.f, xn=0.f, hr=0.f, hz=0.f, hn=0.f;
    #pragma unroll
    for (int ks = 0; ks < 4; ks++){
        const float* gi = g_gpart + (size_t)(ks*64 + b)*G3;
        const float* gh = g_gpart + (size_t)((4+ks)*64 + b)*G3;
        xr += gi[j]; xz += gi[1024+j]; xn += gi[2048+j];
        hr += gh[j]; hz += gh[1024+j]; hn += gh[2048+j];
    }
    xr += bi[j]; xz += bi[1024+j]; xn += bi[2048+j];
    hr += bh[j]; hz += bh[1024+j]; hn += bh[2048+j];
    float rr = 1.f/(1.f + expf(-(xr+hr)));
    float zg = 1.f/(1.f + expf(-(xz+hz)));
    float nn = tanhf(xn + rr*hn);
    float h  = (1.f - zg)*nn + zg*hprev[idx];
    hout[idx] = h;
    __nv_bfloat16 hi, lo; split1(h, &hi, &lo);
    if (layer == 0){ g_h0hi[idx] = hi; g_h0lo[idx] = lo; }
    else { g_cathi[b*2048 + j] = hi; g_catlo[b*2048 + j] = lo; g_h1[idx] = h; }
}

// ---------------- attention pass 1: branchless online softmax, depth-2 reg prefetch ----------------
__global__ void __launch_bounds__(128, 3) attn_pass_k(const float* __restrict__ enc)
{
    __shared__ float4 shv[256];        // h1 for this batch row
    __shared__ float4 cbuf4[4][256];
    __shared__ float sm_m[4], sm_s[4];

    int b = blockIdx.y, cch = blockIdx.x;
    int tid = threadIdx.x, w = tid >> 5, lane = tid & 31;

    for (int i = tid; i < 256; i += 128) shv[i] = ((const float4*)g_h1)[b*256 + i];
    __syncthreads();

    float4 ctx[8];
    #pragma unroll
    for (int k = 0; k < 8; k++) ctx[k] = make_float4(0.f,0.f,0.f,0.f);
    float m = -1e30f, ssum = 0.f;

    const float4* ebase = (const float4*)(enc + ((size_t)b*LSEQ + cch*ACH + w*16)*1024);
    uint32_t hvad = (uint32_t)__cvta_generic_to_shared(&shv[lane]);

    float4 buf0[8], buf1[8], buf2[8];
    #pragma unroll
    for (int k = 0; k < 8; k++) buf0[k] = ebase[lane + 32*k];
    #pragma unroll
    for (int k = 0; k < 8; k++) buf1[k] = ebase[256 + lane + 32*k];

    #pragma unroll
    for (int i = 0; i < 16; i++){
        float4* cur = (i%3==0) ? buf0 : ((i%3==1) ? buf1 : buf2);
        float4* nxt = ((i+2)%3==0) ? buf0 : (((i+2)%3==1) ? buf1 : buf2);
        if (i + 2 < 16){
            const float4* src = ebase + (size_t)(i+2)*256;
            #pragma unroll
            for (int k = 0; k < 8; k++) nxt[k] = src[lane + 32*k];
        }
        float d0=0.f, d1=0.f, d2=0.f, d3=0.f;
        #pragma unroll
        for (int k = 0; k < 8; k++){
            float4 hvk;
            asm volatile("ld.shared.v4.f32 {%0,%1,%2,%3}, [%4];"
                : "=f"(hvk.x), "=f"(hvk.y), "=f"(hvk.z), "=f"(hvk.w)
                : "r"(hvad + (uint32_t)(k*512)));
            d0 = fmaf(cur[k].x, hvk.x, d0);
            d1 = fmaf(cur[k].y, hvk.y, d1);
            d2 = fmaf(cur[k].z, hvk.z, d2);
            d3 = fmaf(cur[k].w, hvk.w, d3);
        }
        float d = (d0 + d1) + (d2 + d3);
        #pragma unroll
        for (int off = 16; off; off >>= 1) d += __shfl_xor_sync(0xffffffffu, d, off);
        if (lane == 0) g_scores[b*LSEQ + cch*ACH + w*16 + i] = d;
        float mn = fmaxf(m, d);
        float sc = __expf(m - mn);
        float wg = __expf(d - mn);
        ssum = ssum * sc + wg;
        m = mn;
        #pragma unroll
        for (int k = 0; k < 8; k++){
            ctx[k].x = fmaf(ctx[k].x, sc, wg*cur[k].x);
            ctx[k].y = fmaf(ctx[k].y, sc, wg*cur[k].y);
            ctx[k].z = fmaf(ctx[k].z, sc, wg*cur[k].z);
            ctx[k].w = fmaf(ctx[k].w, sc, wg*cur[k].w);
        }
    }

    if (lane == 0){ sm_m[w] = m; sm_s[w] = ssum; }
    __syncthreads();
    float mb = fmaxf(fmaxf(sm_m[0], sm_m[1]), fmaxf(sm_m[2], sm_m[3]));
    float sce = __expf(m - mb);
    #pragma unroll
    for (int k = 0; k < 8; k++)
        cbuf4[w][lane + 32*k] = make_float4(ctx[k].x*sce, ctx[k].y*sce, ctx[k].z*sce, ctx[k].w*sce);
    __syncthreads();
    const float* cb = (const float*)cbuf4;
    for (int e = tid; e < 1024; e += 128){
        float s = cb[e] + cb[1024 + e] + cb[2048 + e] + cb[3072 + e];
        g_pctx[(size_t)(b*32 + cch)*1024 + e] = s;
    }
    if (tid == 0){
        float zb = 0.f;
        #pragma unroll
        for (int jw = 0; jw < 4; jw++) zb += sm_s[jw]*__expf(sm_m[jw] - mb);
        g_pm[b*32 + cch] = mb; g_ps[b*32 + cch] = zb;
    }
}

// ---------------- attention finalize ----------------
__global__ void attn_fin_k(float* __restrict__ out_attn)
{
    __shared__ float we[32];
    int b = blockIdx.x, tid = threadIdx.x;
    float M = -1e30f;
    #pragma unroll
    for (int cc = 0; cc < 32; cc++) M = fmaxf(M, g_pm[b*32 + cc]);
    float Z = 0.f;
    #pragma unroll
    for (int cc = 0; cc < 32; cc++) Z += g_ps[b*32 + cc]*__expf(g_pm[b*32 + cc] - M);
    float inv = 1.f / Z;
    if (tid < 32) we[tid] = __expf(g_pm[b*32 + tid] - M);
    __syncthreads();
    for (int l = tid; l < LSEQ; l += 256)
        out_attn[b*LSEQ + l] = __expf(g_scores[b*LSEQ + l] - M) * inv;
    for (int e = tid; e < 1024; e += 256){
        float s = 0.f;
        #pragma unroll
        for (int cc = 0; cc < 32; cc++)
            s += we[cc] * g_pctx[(size_t)(b*32 + cc)*1024 + e];
        float v = s * inv;
        __nv_bfloat16 hi, lo; split1(v, &hi, &lo);
        g_cathi[b*2048 + 1024 + e] = hi; g_catlo[b*2048 + 1024 + e] = lo;
    }
}

// ---------------- Wc combine ----------------
__global__ void cc_comb_k(const float* __restrict__ bc)
{
    int idx = blockIdx.x*256 + threadIdx.x;  // 65536
    int b = idx >> 10, n = idx & 1023;
    float s = bc[n];
    #pragma unroll
    for (int z = 0; z < 16; z++) s += g_ccpart[(size_t)(z*64 + b)*1024 + n];
    float v = tanhf(s);
    __nv_bfloat16 hi, lo; split1(v, &hi, &lo);
    g_cchi[idx] = hi; g_cclo[idx] = lo;
}

// ---------------- launch ----------------
extern "C" void kernel_launch(void* const* d_in, const int* in_sizes, int n_in,
                              void* d_out, int out_size)
{
    const int*   seq  = (const int*)d_in[0];
    const float* lh   = (const float*)d_in[1];
    const float* enc  = (const float*)d_in[2];
    const float* emb  = (const float*)d_in[3];
    const float* Wih0 = (const float*)d_in[4];
    const float* Whh0 = (const float*)d_in[5];
    const float* bih0 = (const float*)d_in[6];
    const float* bhh0 = (const float*)d_in[7];
    const float* Wih1 = (const float*)d_in[8];
    const float* Whh1 = (const float*)d_in[9];
    const float* bih1 = (const float*)d_in[10];
    const float* bhh1 = (const float*)d_in[11];
    const float* Wc   = (const float*)d_in[12];
    const float* bc   = (const float*)d_in[13];
    const float* Wout = (const float*)d_in[14];
    const float* bout = (const float*)d_in[15];

    float* out        = (float*)d_out;
    float* out_logits = out;                                   // [64, 32000]
    float* out_hidden = out + (size_t)BATCH*NVOC;              // [2, 64, 1024]
    float* out_attn   = out_hidden + 2*BATCH*HDIM;             // [64, 1, 2048]

    cudaFuncSetAttribute(gemm2_k, cudaFuncAttributeMaxDynamicSharedMemorySize, GSMEM);

    prep_k<<<768, 256>>>(seq, emb, lh);

    gemm2_k<<<dim3(24, 2, 4), 256, GSMEM>>>(Wih0, Whh0, nullptr, nullptr, 1024, G3, 256, 0);
    gru_cell_k<<<256, 256>>>(bih0, bhh0, lh, out_hidden, 0);

    gemm2_k<<<dim3(24, 2, 4), 256, GSMEM>>>(Wih1, Whh1, nullptr, nullptr, 1024, G3, 256, 1);
    gru_cell_k<<<256, 256>>>(bih1, bhh1, lh + BATCH*HDIM, out_hidden + BATCH*HDIM, 1);

    attn_pass_k<<<dim3(32, 64), 128>>>(enc);
    attn_fin_k<<<64, 256>>>(out_attn);

    gemm2_k<<<dim3(8, 1, 16), 256, GSMEM>>>(Wc, nullptr, nullptr, nullptr, 2048, 1024, 128, 2);
    cc_comb_k<<<256, 256>>>(bc);

    gemm2_k<<<dim3(250, 1, 1), 256, GSMEM>>>(Wout, nullptr, bout, out_logits, 1024, NVOC, 1024, 3);
}

// round 8
// speedup vs baseline: 1.0507x; 1.0390x over previous
#include <cuda_runtime.h>
#include <cuda_bf16.h>
#include <cstdint>

#define BATCH 64
#define HDIM  1024
#define LSEQ  2048
#define NVOC  32000
#define G3    3072

// ---------------- scratch (device globals; no allocation) ----------------
__device__ __nv_bfloat16 g_xhi[BATCH*HDIM],  g_xlo[BATCH*HDIM];
__device__ __nv_bfloat16 g_hphi[2*BATCH*HDIM], g_hplo[2*BATCH*HDIM];
__device__ __nv_bfloat16 g_h0hi[BATCH*HDIM], g_h0lo[BATCH*HDIM];
__device__ float         g_gpart[8*BATCH*G3];     // [y*4+z][64][3072]
__device__ float         g_h1[BATCH*HDIM];
__device__ __nv_bfloat16 g_cathi[BATCH*2*HDIM], g_catlo[BATCH*2*HDIM];
__device__ float         g_scores[BATCH*LSEQ];
__device__ float         g_pm[BATCH*16], g_ps[BATCH*16];
__device__ float         g_pctx[BATCH*16*HDIM];
__device__ float         g_ccpart[8*BATCH*HDIM]; // [z][64][1024]
__device__ __nv_bfloat16 g_cchi[BATCH*HDIM], g_cclo[BATCH*HDIM];

// ---------------- helpers ----------------
__device__ __forceinline__ uint32_t pk_hi(float x, float y){
    return (__float_as_uint(x) >> 16) | (__float_as_uint(y) & 0xffff0000u);
}
__device__ __forceinline__ uint32_t pk_lo(float x, float y){
    float rx = x - __uint_as_float(__float_as_uint(x) & 0xffff0000u);
    float ry = y - __uint_as_float(__float_as_uint(y) & 0xffff0000u);
    return (__float_as_uint(rx) >> 16) | (__float_as_uint(ry) & 0xffff0000u);
}
__device__ __forceinline__ void split1(float v, __nv_bfloat16* hi, __nv_bfloat16* lo){
    uint32_t u  = __float_as_uint(v);
    uint32_t uh = u & 0xffff0000u;
    float r = v - __uint_as_float(uh);
    *hi = __ushort_as_bfloat16((unsigned short)(uh >> 16));
    *lo = __ushort_as_bfloat16((unsigned short)(__float_as_uint(r) >> 16));
}
__device__ __forceinline__ void mma16816(float* c, const uint32_t* a, uint32_t b0, uint32_t b1){
    asm volatile("mma.sync.aligned.m16n8k16.row.col.f32.bf16.bf16.f32 "
        "{%0,%1,%2,%3}, {%4,%5,%6,%7}, {%8,%9}, {%0,%1,%2,%3};"
        : "+f"(c[0]), "+f"(c[1]), "+f"(c[2]), "+f"(c[3])
        : "r"(a[0]), "r"(a[1]), "r"(a[2]), "r"(a[3]), "r"(b0), "r"(b1));
}
__device__ __forceinline__ void ldsm4(uint32_t* d, uint32_t saddr){
    asm volatile("ldmatrix.sync.aligned.m8n8.x4.shared.b16 {%0,%1,%2,%3}, [%4];"
        : "=r"(d[0]), "=r"(d[1]), "=r"(d[2]), "=r"(d[3]) : "r"(saddr));
}
__device__ __forceinline__ void cp16(void* sdst, const void* gsrc){
    uint32_t s = (uint32_t)__cvta_generic_to_shared(sdst);
    asm volatile("cp.async.cg.shared.global [%0], [%1], 16;" :: "r"(s), "l"(gsrc));
}

// ---------------- prep: embed gather + hi/lo split of x and h_prev ----------------
__global__ void prep_k(const int* __restrict__ seq, const float* __restrict__ embed,
                       const float* __restrict__ lh)
{
    int idx = blockIdx.x*256 + threadIdx.x;     // 3 * 65536
    int z = idx >> 16, r = idx & 65535;
    float v;
    if (z == 0){
        int b = r >> 10, j = r & 1023;
        v = embed[(size_t)seq[b]*HDIM + j];
    } else {
        v = lh[(size_t)(z-1)*BATCH*HDIM + r];
    }
    __nv_bfloat16 hi, lo; split1(v, &hi, &lo);
    if (z == 0){ g_xhi[r] = hi; g_xlo[r] = lo; }
    else       { g_hphi[(z-1)*BATCH*HDIM + r] = hi; g_hplo[(z-1)*BATCH*HDIM + r] = lo; }
}

// ---------------- gemm3: warp-autonomous pipelines, sectioned A slab ----------------
// out = act(64xK) @ W(NxK)^T over K-range [zz*KS, (zz+1)*KS)
// A (pre-split bf16 hi/lo) staged per 128-K section, double buffered, one barrier/section.
// W staged per-warp (16 rows x 32 f32), 2 stages, cp.async pipeline, no barriers in loop.
// mode 0/1: GRU layer 0/1 -> g_gpart   mode 2: Wc -> g_ccpart   mode 3: Wout+bias -> out_ext
//
// SMEM layout (bytes):
//  A hi buf0: 0      A lo buf0: 17408   A hi buf1: 34816   A lo buf1: 52224  (row stride 272)
//  W: 69632 + w*5120 + stage*2560  (row stride 160)
#define GSMEM3 110592
__global__ void __launch_bounds__(256, 2)
gemm3_k(const float* __restrict__ W0, const float* __restrict__ W1,
        const float* __restrict__ bias, float* __restrict__ out_ext,
        int K, int N, int KS, int mode)
{
    extern __shared__ char sraw[];
    uint32_t sb = (uint32_t)__cvta_generic_to_shared(sraw);

    int y = blockIdx.y, zz = blockIdx.z;
    const float* W = y ? W1 : W0;
    const __nv_bfloat16 *Ahp, *Alp;
    float* op;
    if (mode == 0){ Ahp = y ? g_hphi : g_xhi;  Alp = y ? g_hplo : g_xlo;  op = g_gpart; }
    else if (mode == 1){
        Ahp = y ? (g_hphi + BATCH*HDIM) : g_h0hi;
        Alp = y ? (g_hplo + BATCH*HDIM) : g_h0lo;  op = g_gpart;
    } else if (mode == 2){ Ahp = g_cathi; Alp = g_catlo; op = g_ccpart; }
    else { Ahp = g_cchi;  Alp = g_cclo;  op = out_ext; }
    const uint32_t* Agh = (const uint32_t*)Ahp;
    const uint32_t* Agl = (const uint32_t*)Alp;

    int tid = threadIdx.x, w = tid >> 5, lane = tid & 31;
    int r = lane >> 2, c = lane & 3;
    int nblk = blockIdx.x * 128;
    int K2 = K >> 1;
    int kbeg = zz * KS;
    int nchunk = KS >> 5;
    int nsec = KS >> 7;

    // ldmatrix lane offset within A slab (row stride 272B)
    uint32_t aoff = (uint32_t)((lane & 15)*272 + (lane >> 4)*16);
    // per-warp W row base in gmem
    const float* Wwarp = W + (size_t)(nblk + w*16)*K;

    // cooperative A-section load: section s -> buffer b (issue only, no commit)
    auto loadA = [&](int s, int b){
        int ku = (kbeg + s*128) >> 1;    // u32 column offset
        #pragma unroll
        for (int i = 0; i < 4; i++){
            int p = tid + i*256;         // 0..1023
            int row = p >> 4, c16 = p & 15;
            const uint32_t* sh = Agh + (size_t)row*K2 + ku + c16*4;
            const uint32_t* sl = Agl + (size_t)row*K2 + ku + c16*4;
            cp16(sraw + b*34816 + row*272 + c16*16, sh);
            cp16(sraw + b*34816 + 17408 + row*272 + c16*16, sl);
        }
    };
    // per-warp W chunk load: chunk g -> stage st (issue only, no commit)
    auto issueW = [&](int g, int st){
        int kco = kbeg + g*32;
        char* wd = sraw + 69632 + w*5120 + st*2560;
        #pragma unroll
        for (int j = 0; j < 4; j++){
            int q = lane + j*32;         // 0..127
            int row = q >> 3, c8 = q & 7;
            cp16(wd + row*160 + c8*16, Wwarp + (size_t)row*K + kco + c8*4);
        }
    };

    float acc[4][2][4];
    #pragma unroll
    for (int i=0;i<4;i++)
        #pragma unroll
        for (int j=0;j<2;j++)
            #pragma unroll
            for (int q=0;q<4;q++) acc[i][j][q] = 0.f;

    // prologue: A section 0 + W chunk 0 in group 0; W chunk 1 in group 1
    loadA(0, 0);
    issueW(0, 0);
    asm volatile("cp.async.commit_group;");
    issueW(1, 1);
    asm volatile("cp.async.commit_group;");

    for (int g = 0; g < nchunk; g++){
        if (g == nchunk - 1) asm volatile("cp.async.wait_group 0;");
        else                 asm volatile("cp.async.wait_group 1;");
        __syncwarp();
        if ((g & 3) == 0) __syncthreads();   // section barrier (A slab visible; prev section drained)

        // ---- compute chunk g ----
        {
            int bufA = (g >> 2) & 1;
            uint32_t cloc = (uint32_t)((g & 3) * 64);
            uint32_t aHb = sb + bufA*34816 + aoff + cloc;
            uint32_t aLb = aHb + 17408;
            const float2* wst = (const float2*)(sraw + 69632 + w*5120 + (g & 1)*2560);

            #pragma unroll
            for (int ki = 0; ki < 2; ki++){
                uint32_t bh[2][2], bl[2][2];
                #pragma unroll
                for (int nt = 0; nt < 2; nt++){
                    int nl = nt*8 + r;
                    const float2* wp = wst + nl*20 + ki*8 + c;
                    float2 w0 = wp[0], w1 = wp[4];
                    bh[nt][0] = pk_hi(w0.x, w0.y);  bl[nt][0] = pk_lo(w0.x, w0.y);
                    bh[nt][1] = pk_hi(w1.x, w1.y);  bl[nt][1] = pk_lo(w1.x, w1.y);
                }
                #pragma unroll
                for (int mt = 0; mt < 4; mt++){
                    uint32_t ah[4], aw[4];
                    ldsm4(ah, aHb + mt*4352 + ki*32);
                    ldsm4(aw, aLb + mt*4352 + ki*32);
                    #pragma unroll
                    for (int nt = 0; nt < 2; nt++){
                        mma16816(acc[mt][nt], ah, bh[nt][0], bh[nt][1]);
                        mma16816(acc[mt][nt], aw, bh[nt][0], bh[nt][1]);
                        mma16816(acc[mt][nt], ah, bl[nt][0], bl[nt][1]);
                    }
                }
            }
        }

        // ---- issue next loads (after compute: stage g&1 now free) ----
        bool did = false;
        if ((g & 3) == 0 && (g >> 2) + 1 < nsec){
            loadA((g >> 2) + 1, ((g >> 2) + 1) & 1);   // safe: all warps passed this section's barrier
            did = true;
        }
        if (g + 2 < nchunk){
            issueW(g + 2, (g + 2) & 1);
            did = true;
        }
        if (did) asm volatile("cp.async.commit_group;");
    }

    int nw = nblk + w*16, cq = c*2;
    if (mode < 3){
        float* o = op + (size_t)((y*gridDim.z + zz) * 64) * N;
        #pragma unroll
        for (int mt = 0; mt < 4; mt++)
            #pragma unroll
            for (int nt = 0; nt < 2; nt++){
                int row = mt*16 + r, col = nw + nt*8 + cq;
                *(float2*)(o + (size_t)row*N + col)     = make_float2(acc[mt][nt][0], acc[mt][nt][1]);
                *(float2*)(o + (size_t)(row+8)*N + col) = make_float2(acc[mt][nt][2], acc[mt][nt][3]);
            }
    } else {
        #pragma unroll
        for (int mt = 0; mt < 4; mt++)
            #pragma unroll
            for (int nt = 0; nt < 2; nt++){
                int row = mt*16 + r, col = nw + nt*8 + cq;
                float2 bb = *(const float2*)(bias + col);
                *(float2*)(out_ext + (size_t)row*N + col)     = make_float2(acc[mt][nt][0] + bb.x, acc[mt][nt][1] + bb.y);
                *(float2*)(out_ext + (size_t)(row+8)*N + col) = make_float2(acc[mt][nt][2] + bb.x, acc[mt][nt][3] + bb.y);
            }
    }
}

// ---------------- GRU elementwise cell (4 split-K partials) ----------------
__global__ void gru_cell_k(const float* __restrict__ bi, const float* __restrict__ bh,
                           const float* __restrict__ hprev, float* __restrict__ hout,
                           int layer)
{
    int idx = blockIdx.x*256 + threadIdx.x;   // 65536
    int b = idx >> 10, j = idx & 1023;
    float xr=0.f, xz=0.f, xn=0.f, hr=0.f, hz=0.f, hn=0.f;
    #pragma unroll
    for (int ks = 0; ks < 4; ks++){
        const float* gi = g_gpart + (size_t)(ks*64 + b)*G3;
        const float* gh = g_gpart + (size_t)((4+ks)*64 + b)*G3;
        xr += gi[j]; xz += gi[1024+j]; xn += gi[2048+j];
        hr += gh[j]; hz += gh[1024+j]; hn += gh[2048+j];
    }
    xr += bi[j]; xz += bi[1024+j]; xn += bi[2048+j];
    hr += bh[j]; hz += bh[1024+j]; hn += bh[2048+j];
    float rr = 1.f/(1.f + expf(-(xr+hr)));
    float zg = 1.f/(1.f + expf(-(xz+hz)));
    float nn = tanhf(xn + rr*hn);
    float h  = (1.f - zg)*nn + zg*hprev[idx];
    hout[idx] = h;
    __nv_bfloat16 hi, lo; split1(h, &hi, &lo);
    if (layer == 0){ g_h0hi[idx] = hi; g_h0lo[idx] = lo; }
    else { g_cathi[b*2048 + j] = hi; g_catlo[b*2048 + j] = lo; g_h1[idx] = h; }
}

// ---------------- attention pass 1 (R4 version): cp.async row double-buffer ----------------
#define ASMEM 69760
__global__ void __launch_bounds__(256, 2) attn_pass_k(const float* __restrict__ enc)
{
    extern __shared__ char araw[];
    float* sbuf = (float*)araw;                 // [8 warps][2][1024]
    float* cbuf = sbuf;                         // alias after main loop
    float* smhv = (float*)(araw + 65536);       // [1024]
    float* sm_m = smhv + 1024;                  // [8]
    float* sm_s = sm_m + 8;                     // [8]

    int b = blockIdx.x >> 4, cch = blockIdx.x & 15;
    int tid = threadIdx.x, w = tid >> 5, lane = tid & 31;

    for (int i = tid; i < 1024; i += 256) smhv[i] = g_h1[b*1024 + i];
    __syncthreads();
    float4 hv[8];
    #pragma unroll
    for (int k = 0; k < 8; k++) hv[k] = ((const float4*)smhv)[lane + 32*k];
    float4 ctx[8];
    #pragma unroll
    for (int k = 0; k < 8; k++) ctx[k] = make_float4(0.f,0.f,0.f,0.f);
    float m = -1e30f, ssum = 0.f;

    const float* ebase = enc + ((size_t)b*LSEQ + cch*128 + w*16)*1024;
    float* mybuf = sbuf + w*2048;

    #pragma unroll
    for (int s = 0; s < 8; s++)
        cp16(mybuf + lane*4 + s*128, ebase + lane*4 + s*128);
    asm volatile("cp.async.commit_group;");

    for (int i = 0; i < 16; i++){
        if (i < 15){
            const float* src = ebase + (size_t)(i+1)*1024;
            float* dst = mybuf + ((i+1)&1)*1024;
            #pragma unroll
            for (int s = 0; s < 8; s++)
                cp16(dst + lane*4 + s*128, src + lane*4 + s*128);
            asm volatile("cp.async.commit_group;");
            asm volatile("cp.async.wait_group 1;");
        } else {
            asm volatile("cp.async.wait_group 0;");
        }
        const float4* v4 = (const float4*)(mybuf + (i&1)*1024);
        float4 v[8];
        #pragma unroll
        for (int k = 0; k < 8; k++) v[k] = v4[lane + 32*k];
        float d = 0.f;
        #pragma unroll
        for (int k = 0; k < 8; k++){
            d = fmaf(v[k].x, hv[k].x, d); d = fmaf(v[k].y, hv[k].y, d);
            d = fmaf(v[k].z, hv[k].z, d); d = fmaf(v[k].w, hv[k].w, d);
        }
        #pragma unroll
        for (int off = 16; off; off >>= 1) d += __shfl_xor_sync(0xffffffffu, d, off);
        if (lane == 0) g_scores[b*LSEQ + cch*128 + w*16 + i] = d;
        if (d > m){
            float sc = __expf(m - d);
            ssum *= sc;
            #pragma unroll
            for (int k = 0; k < 8; k++){
                ctx[k].x *= sc; ctx[k].y *= sc; ctx[k].z *= sc; ctx[k].w *= sc;
            }
            m = d;
        }
        float wg = __expf(d - m);
        ssum += wg;
        #pragma unroll
        for (int k = 0; k < 8; k++){
            ctx[k].x = fmaf(wg, v[k].x, ctx[k].x); ctx[k].y = fmaf(wg, v[k].y, ctx[k].y);
            ctx[k].z = fmaf(wg, v[k].z, ctx[k].z); ctx[k].w = fmaf(wg, v[k].w, ctx[k].w);
        }
    }

    if (lane == 0){ sm_m[w] = m; sm_s[w] = ssum; }
    __syncthreads();
    float mb = sm_m[0];
    #pragma unroll
    for (int jw = 1; jw < 8; jw++) mb = fmaxf(mb, sm_m[jw]);
    float sc = __expf(m - mb);
    #pragma unroll
    for (int k = 0; k < 8; k++){
        int e2 = (lane + 32*k)*4;
        cbuf[w*1024 + e2+0] = ctx[k].x*sc; cbuf[w*1024 + e2+1] = ctx[k].y*sc;
        cbuf[w*1024 + e2+2] = ctx[k].z*sc; cbuf[w*1024 + e2+3] = ctx[k].w*sc;
    }
    __syncthreads();
    for (int e2 = tid; e2 < 1024; e2 += 256){
        float s = 0.f;
        #pragma unroll
        for (int jw = 0; jw < 8; jw++) s += cbuf[jw*1024 + e2];
        g_pctx[(size_t)(b*16 + cch)*1024 + e2] = s;
    }
    if (tid == 0){
        float zb = 0.f;
        #pragma unroll
        for (int jw = 0; jw < 8; jw++) zb += sm_s[jw]*__expf(sm_m[jw] - mb);
        g_pm[b*16 + cch] = mb; g_ps[b*16 + cch] = zb;
    }
}

// ---------------- attention finalize ----------------
__global__ void attn_fin_k(float* __restrict__ out_attn)
{
    int b = blockIdx.x, tid = threadIdx.x;
    float M = -1e30f;
    #pragma unroll
    for (int cc = 0; cc < 16; cc++) M = fmaxf(M, g_pm[b*16 + cc]);
    float Z = 0.f;
    #pragma unroll
    for (int cc = 0; cc < 16; cc++) Z += g_ps[b*16 + cc]*__expf(g_pm[b*16 + cc] - M);
    float inv = 1.f / Z;
    for (int l = tid; l < LSEQ; l += 256)
        out_attn[b*LSEQ + l] = __expf(g_scores[b*LSEQ + l] - M) * inv;
    for (int e = tid; e < 1024; e += 256){
        float s = 0.f;
        #pragma unroll
        for (int cc = 0; cc < 16; cc++)
            s += __expf(g_pm[b*16 + cc] - M) * g_pctx[(size_t)(b*16 + cc)*1024 + e];
        float v = s * inv;
        __nv_bfloat16 hi, lo; split1(v, &hi, &lo);
        g_cathi[b*2048 + 1024 + e] = hi; g_catlo[b*2048 + 1024 + e] = lo;
    }
}

// ---------------- Wc combine ----------------
__global__ void cc_comb_k(const float* __restrict__ bc)
{
    int idx = blockIdx.x*256 + threadIdx.x;  // 65536
    int b = idx >> 10, n = idx & 1023;
    float s = bc[n];
    #pragma unroll
    for (int z = 0; z < 8; z++) s += g_ccpart[(size_t)(z*64 + b)*1024 + n];
    float v = tanhf(s);
    __nv_bfloat16 hi, lo; split1(v, &hi, &lo);
    g_cchi[idx] = hi; g_cclo[idx] = lo;
}

// ---------------- launch ----------------
extern "C" void kernel_launch(void* const* d_in, const int* in_sizes, int n_in,
                              void* d_out, int out_size)
{
    const int*   seq  = (const int*)d_in[0];
    const float* lh   = (const float*)d_in[1];
    const float* enc  = (const float*)d_in[2];
    const float* emb  = (const float*)d_in[3];
    const float* Wih0 = (const float*)d_in[4];
    const float* Whh0 = (const float*)d_in[5];
    const float* bih0 = (const float*)d_in[6];
    const float* bhh0 = (const float*)d_in[7];
    const float* Wih1 = (const float*)d_in[8];
    const float* Whh1 = (const float*)d_in[9];
    const float* bih1 = (const float*)d_in[10];
    const float* bhh1 = (const float*)d_in[11];
    const float* Wc   = (const float*)d_in[12];
    const float* bc   = (const float*)d_in[13];
    const float* Wout = (const float*)d_in[14];
    const float* bout = (const float*)d_in[15];

    float* out        = (float*)d_out;
    float* out_logits = out;                                   // [64, 32000]
    float* out_hidden = out + (size_t)BATCH*NVOC;              // [2, 64, 1024]
    float* out_attn   = out_hidden + 2*BATCH*HDIM;             // [64, 1, 2048]

    cudaFuncSetAttribute(gemm3_k, cudaFuncAttributeMaxDynamicSharedMemorySize, GSMEM3);
    cudaFuncSetAttribute(attn_pass_k, cudaFuncAttributeMaxDynamicSharedMemorySize, ASMEM);

    prep_k<<<768, 256>>>(seq, emb, lh);

    gemm3_k<<<dim3(24, 2, 4), 256, GSMEM3>>>(Wih0, Whh0, nullptr, nullptr, 1024, G3, 256, 0);
    gru_cell_k<<<256, 256>>>(bih0, bhh0, lh, out_hidden, 0);

    gemm3_k<<<dim3(24, 2, 4), 256, GSMEM3>>>(Wih1, Whh1, nullptr, nullptr, 1024, G3, 256, 1);
    gru_cell_k<<<256, 256>>>(bih1, bhh1, lh + BATCH*HDIM, out_hidden + BATCH*HDIM, 1);

    attn_pass_k<<<1024, 256, ASMEM>>>(enc);
    attn_fin_k<<<64, 256>>>(out_attn);

    gemm3_k<<<dim3(8, 1, 8), 256, GSMEM3>>>(Wc, nullptr, nullptr, nullptr, 2048, 1024, 256, 2);
    cc_comb_k<<<256, 256>>>(bc);

    gemm3_k<<<dim3(250, 1, 1), 256, GSMEM3>>>(Wout, nullptr, bout, out_logits, 1024, NVOC, 1024, 3);
}

// round 9
// speedup vs baseline: 1.0631x; 1.0118x over previous
#include <cuda_runtime.h>
#include <cuda_bf16.h>
#include <cstdint>

#define BATCH 64
#define HDIM  1024
#define LSEQ  2048
#define NVOC  32000
#define G3    3072

// ---------------- scratch (device globals; no allocation) ----------------
__device__ __nv_bfloat16 g_xhi[BATCH*HDIM],  g_xlo[BATCH*HDIM];
__device__ __nv_bfloat16 g_hphi[2*BATCH*HDIM], g_hplo[2*BATCH*HDIM];
__device__ __nv_bfloat16 g_h0hi[BATCH*HDIM], g_h0lo[BATCH*HDIM];
__device__ float         g_gpart[8*BATCH*G3];     // [y*4+z][64][3072]
__device__ float         g_h1[BATCH*HDIM];
__device__ __nv_bfloat16 g_cathi[BATCH*2*HDIM], g_catlo[BATCH*2*HDIM];
__device__ float         g_scores[BATCH*LSEQ];
__device__ float         g_pm[BATCH*16], g_ps[BATCH*16];
__device__ float         g_pctx[BATCH*16*HDIM];
__device__ float         g_ccpart[8*BATCH*HDIM]; // [z][64][1024]
__device__ __nv_bfloat16 g_cchi[BATCH*HDIM], g_cclo[BATCH*HDIM];

// ---------------- helpers ----------------
__device__ __forceinline__ uint32_t pk_hi(float x, float y){
    return (__float_as_uint(x) >> 16) | (__float_as_uint(y) & 0xffff0000u);
}
__device__ __forceinline__ uint32_t pk_lo(float x, float y){
    float rx = x - __uint_as_float(__float_as_uint(x) & 0xffff0000u);
    float ry = y - __uint_as_float(__float_as_uint(y) & 0xffff0000u);
    return (__float_as_uint(rx) >> 16) | (__float_as_uint(ry) & 0xffff0000u);
}
__device__ __forceinline__ void split1(float v, __nv_bfloat16* hi, __nv_bfloat16* lo){
    uint32_t u  = __float_as_uint(v);
    uint32_t uh = u & 0xffff0000u;
    float r = v - __uint_as_float(uh);
    *hi = __ushort_as_bfloat16((unsigned short)(uh >> 16));
    *lo = __ushort_as_bfloat16((unsigned short)(__float_as_uint(r) >> 16));
}
__device__ __forceinline__ void mma16816(float* c, const uint32_t* a, uint32_t b0, uint32_t b1){
    asm volatile("mma.sync.aligned.m16n8k16.row.col.f32.bf16.bf16.f32 "
        "{%0,%1,%2,%3}, {%4,%5,%6,%7}, {%8,%9}, {%0,%1,%2,%3};"
        : "+f"(c[0]), "+f"(c[1]), "+f"(c[2]), "+f"(c[3])
        : "r"(a[0]), "r"(a[1]), "r"(a[2]), "r"(a[3]), "r"(b0), "r"(b1));
}
__device__ __forceinline__ void ldsm4(uint32_t* d, uint32_t saddr){
    asm volatile("ldmatrix.sync.aligned.m8n8.x4.shared.b16 {%0,%1,%2,%3}, [%4];"
        : "=r"(d[0]), "=r"(d[1]), "=r"(d[2]), "=r"(d[3]) : "r"(saddr));
}
__device__ __forceinline__ void cp16(void* sdst, const void* gsrc){
    uint32_t s = (uint32_t)__cvta_generic_to_shared(sdst);
    asm volatile("cp.async.cg.shared.global [%0], [%1], 16;" :: "r"(s), "l"(gsrc));
}

// ---------------- prep: embed gather + hi/lo split of x and h_prev ----------------
__global__ void prep_k(const int* __restrict__ seq, const float* __restrict__ embed,
                       const float* __restrict__ lh)
{
    int idx = blockIdx.x*256 + threadIdx.x;     // 3 * 65536
    int z = idx >> 16, r = idx & 65535;
    float v;
    if (z == 0){
        int b = r >> 10, j = r & 1023;
        v = embed[(size_t)seq[b]*HDIM + j];
    } else {
        v = lh[(size_t)(z-1)*BATCH*HDIM + r];
    }
    __nv_bfloat16 hi, lo; split1(v, &hi, &lo);
    if (z == 0){ g_xhi[r] = hi; g_xlo[r] = lo; }
    else       { g_hphi[(z-1)*BATCH*HDIM + r] = hi; g_hplo[(z-1)*BATCH*HDIM + r] = lo; }
}

// ---------------- gemm3: warp-autonomous pipelines, sectioned A slab ----------------
// out = act(64xK) @ W(NxK)^T over K-range [zz*KS, (zz+1)*KS)
// A (pre-split bf16 hi/lo) staged per 128-K section, double buffered, one barrier/section.
// W staged per-warp (16 rows x 32 f32), 2 stages, cp.async pipeline, no barriers in loop.
// mode 0/1: GRU layer 0/1 -> g_gpart   mode 2: Wc -> g_ccpart   mode 3: Wout+bias -> out_ext
//
// SMEM layout (bytes):
//  A hi buf0: 0      A lo buf0: 17408   A hi buf1: 34816   A lo buf1: 52224  (row stride 272)
//  W: 69632 + w*5120 + stage*2560  (row stride 160)
#define GSMEM3 110592
__global__ void __launch_bounds__(256, 2)
gemm3_k(const float* __restrict__ W0, const float* __restrict__ W1,
        const float* __restrict__ bias, float* __restrict__ out_ext,
        int K, int N, int KS, int mode)
{
    extern __shared__ char sraw[];
    uint32_t sb = (uint32_t)__cvta_generic_to_shared(sraw);

    int y = blockIdx.y, zz = blockIdx.z;
    const float* W = y ? W1 : W0;
    const __nv_bfloat16 *Ahp, *Alp;
    float* op;
    if (mode == 0){ Ahp = y ? g_hphi : g_xhi;  Alp = y ? g_hplo : g_xlo;  op = g_gpart; }
    else if (mode == 1){
        Ahp = y ? (g_hphi + BATCH*HDIM) : g_h0hi;
        Alp = y ? (g_hplo + BATCH*HDIM) : g_h0lo;  op = g_gpart;
    } else if (mode == 2){ Ahp = g_cathi; Alp = g_catlo; op = g_ccpart; }
    else { Ahp = g_cchi;  Alp = g_cclo;  op = out_ext; }
    const uint32_t* Agh = (const uint32_t*)Ahp;
    const uint32_t* Agl = (const uint32_t*)Alp;

    int tid = threadIdx.x, w = tid >> 5, lane = tid & 31;
    int r = lane >> 2, c = lane & 3;
    int nblk = blockIdx.x * 128;
    int K2 = K >> 1;
    int kbeg = zz * KS;
    int nchunk = KS >> 5;
    int nsec = KS >> 7;

    // ldmatrix lane offset within A slab (row stride 272B)
    uint32_t aoff = (uint32_t)((lane & 15)*272 + (lane >> 4)*16);
    // per-warp W row base in gmem
    const float* Wwarp = W + (size_t)(nblk + w*16)*K;

    // cooperative A-section load: section s -> buffer b (issue only, no commit)
    auto loadA = [&](int s, int b){
        int ku = (kbeg + s*128) >> 1;    // u32 column offset
        #pragma unroll
        for (int i = 0; i < 4; i++){
            int p = tid + i*256;         // 0..1023
            int row = p >> 4, c16 = p & 15;
            const uint32_t* sh = Agh + (size_t)row*K2 + ku + c16*4;
            const uint32_t* sl = Agl + (size_t)row*K2 + ku + c16*4;
            cp16(sraw + b*34816 + row*272 + c16*16, sh);
            cp16(sraw + b*34816 + 17408 + row*272 + c16*16, sl);
        }
    };
    // per-warp W chunk load: chunk g -> stage st (issue only, no commit)
    auto issueW = [&](int g, int st){
        int kco = kbeg + g*32;
        char* wd = sraw + 69632 + w*5120 + st*2560;
        #pragma unroll
        for (int j = 0; j < 4; j++){
            int q = lane + j*32;         // 0..127
            int row = q >> 3, c8 = q & 7;
            cp16(wd + row*160 + c8*16, Wwarp + (size_t)row*K + kco + c8*4);
        }
    };

    float acc[4][2][4];
    #pragma unroll
    for (int i=0;i<4;i++)
        #pragma unroll
        for (int j=0;j<2;j++)
            #pragma unroll
            for (int q=0;q<4;q++) acc[i][j][q] = 0.f;

    // prologue: A section 0 + W chunk 0 in group 0; W chunk 1 in group 1
    loadA(0, 0);
    issueW(0, 0);
    asm volatile("cp.async.commit_group;");
    issueW(1, 1);
    asm volatile("cp.async.commit_group;");

    for (int g = 0; g < nchunk; g++){
        if (g == nchunk - 1) asm volatile("cp.async.wait_group 0;");
        else                 asm volatile("cp.async.wait_group 1;");
        __syncwarp();
        if ((g & 3) == 0) __syncthreads();   // section barrier (A slab visible; prev section drained)

        // ---- compute chunk g ----
        {
            int bufA = (g >> 2) & 1;
            uint32_t cloc = (uint32_t)((g & 3) * 64);
            uint32_t aHb = sb + bufA*34816 + aoff + cloc;
            uint32_t aLb = aHb + 17408;
            const float2* wst = (const float2*)(sraw + 69632 + w*5120 + (g & 1)*2560);

            #pragma unroll
            for (int ki = 0; ki < 2; ki++){
                uint32_t bh[2][2], bl[2][2];
                #pragma unroll
                for (int nt = 0; nt < 2; nt++){
                    int nl = nt*8 + r;
                    const float2* wp = wst + nl*20 + ki*8 + c;
                    float2 w0 = wp[0], w1 = wp[4];
                    bh[nt][0] = pk_hi(w0.x, w0.y);  bl[nt][0] = pk_lo(w0.x, w0.y);
                    bh[nt][1] = pk_hi(w1.x, w1.y);  bl[nt][1] = pk_lo(w1.x, w1.y);
                }
                #pragma unroll
                for (int mt = 0; mt < 4; mt++){
                    uint32_t ah[4], aw[4];
                    ldsm4(ah, aHb + mt*4352 + ki*32);
                    ldsm4(aw, aLb + mt*4352 + ki*32);
                    #pragma unroll
                    for (int nt = 0; nt < 2; nt++){
                        mma16816(acc[mt][nt], ah, bh[nt][0], bh[nt][1]);
                        mma16816(acc[mt][nt], aw, bh[nt][0], bh[nt][1]);
                        mma16816(acc[mt][nt], ah, bl[nt][0], bl[nt][1]);
                    }
                }
            }
        }

        // ---- issue next loads (after compute: stage g&1 now free) ----
        bool did = false;
        if ((g & 3) == 0 && (g >> 2) + 1 < nsec){
            loadA((g >> 2) + 1, ((g >> 2) + 1) & 1);   // safe: all warps passed this section's barrier
            did = true;
        }
        if (g + 2 < nchunk){
            issueW(g + 2, (g + 2) & 1);
            did = true;
        }
        if (did) asm volatile("cp.async.commit_group;");
    }

    int nw = nblk + w*16, cq = c*2;
    if (mode < 3){
        float* o = op + (size_t)((y*gridDim.z + zz) * 64) * N;
        #pragma unroll
        for (int mt = 0; mt < 4; mt++)
            #pragma unroll
            for (int nt = 0; nt < 2; nt++){
                int row = mt*16 + r, col = nw + nt*8 + cq;
                *(float2*)(o + (size_t)row*N + col)     = make_float2(acc[mt][nt][0], acc[mt][nt][1]);
                *(float2*)(o + (size_t)(row+8)*N + col) = make_float2(acc[mt][nt][2], acc[mt][nt][3]);
            }
    } else {
        #pragma unroll
        for (int mt = 0; mt < 4; mt++)
            #pragma unroll
            for (int nt = 0; nt < 2; nt++){
                int row = mt*16 + r, col = nw + nt*8 + cq;
                float2 bb = *(const float2*)(bias + col);
                *(float2*)(out_ext + (size_t)row*N + col)     = make_float2(acc[mt][nt][0] + bb.x, acc[mt][nt][1] + bb.y);
                *(float2*)(out_ext + (size_t)(row+8)*N + col) = make_float2(acc[mt][nt][2] + bb.x, acc[mt][nt][3] + bb.y);
            }
    }
}

// ---------------- GRU elementwise cell (4 split-K partials) ----------------
__global__ void gru_cell_k(const float* __restrict__ bi, const float* __restrict__ bh,
                           const float* __restrict__ hprev, float* __restrict__ hout,
                           int layer)
{
    int idx = blockIdx.x*256 + threadIdx.x;   // 65536
    int b = idx >> 10, j = idx & 1023;
    float xr=0.f, xz=0.f, xn=0.f, hr=0.f, hz=0.f, hn=0.f;
    #pragma unroll
    for (int ks = 0; ks < 4; ks++){
        const float* gi = g_gpart + (size_t)(ks*64 + b)*G3;
        const float* gh = g_gpart + (size_t)((4+ks)*64 + b)*G3;
        xr += gi[j]; xz += gi[1024+j]; xn += gi[2048+j];
        hr += gh[j]; hz += gh[1024+j]; hn += gh[2048+j];
    }
    xr += bi[j]; xz += bi[1024+j]; xn += bi[2048+j];
    hr += bh[j]; hz += bh[1024+j]; hn += bh[2048+j];
    float rr = 1.f/(1.f + expf(-(xr+hr)));
    float zg = 1.f/(1.f + expf(-(xz+hz)));
    float nn = tanhf(xn + rr*hn);
    float h  = (1.f - zg)*nn + zg*hprev[idx];
    hout[idx] = h;
    __nv_bfloat16 hi, lo; split1(h, &hi, &lo);
    if (layer == 0){ g_h0hi[idx] = hi; g_h0lo[idx] = lo; }
    else { g_cathi[b*2048 + j] = hi; g_catlo[b*2048 + j] = lo; g_h1[idx] = h; }
}

// ---------------- attention pass 1 (R4 version): cp.async row double-buffer ----------------
#define ASMEM 69760
__global__ void __launch_bounds__(256, 2) attn_pass_k(const float* __restrict__ enc)
{
    extern __shared__ char araw[];
    float* sbuf = (float*)araw;                 // [8 warps][2][1024]
    float* cbuf = sbuf;                         // alias after main loop
    float* smhv = (float*)(araw + 65536);       // [1024]
    float* sm_m = smhv + 1024;                  // [8]
    float* sm_s = sm_m + 8;                     // [8]

    int b = blockIdx.x >> 4, cch = blockIdx.x & 15;
    int tid = threadIdx.x, w = tid >> 5, lane = tid & 31;

    for (int i = tid; i < 1024; i += 256) smhv[i] = g_h1[b*1024 + i];
    __syncthreads();
    float4 hv[8];
    #pragma unroll
    for (int k = 0; k < 8; k++) hv[k] = ((const float4*)smhv)[lane + 32*k];
    float4 ctx[8];
    #pragma unroll
    for (int k = 0; k < 8; k++) ctx[k] = make_float4(0.f,0.f,0.f,0.f);
    float m = -1e30f, ssum = 0.f;

    const float* ebase = enc + ((size_t)b*LSEQ + cch*128 + w*16)*1024;
    float* mybuf = sbuf + w*2048;

    #pragma unroll
    for (int s = 0; s < 8; s++)
        cp16(mybuf + lane*4 + s*128, ebase + lane*4 + s*128);
    asm volatile("cp.async.commit_group;");

    for (int i = 0; i < 16; i++){
        if (i < 15){
            const float* src = ebase + (size_t)(i+1)*1024;
            float* dst = mybuf + ((i+1)&1)*1024;
            #pragma unroll
            for (int s = 0; s < 8; s++)
                cp16(dst + lane*4 + s*128, src + lane*4 + s*128);
            asm volatile("cp.async.commit_group;");
            asm volatile("cp.async.wait_group 1;");
        } else {
            asm volatile("cp.async.wait_group 0;");
        }
        const float4* v4 = (const float4*)(mybuf + (i&1)*1024);
        float4 v[8];
        #pragma unroll
        for (int k = 0; k < 8; k++) v[k] = v4[lane + 32*k];
        float d = 0.f;
        #pragma unroll
        for (int k = 0; k < 8; k++){
            d = fmaf(v[k].x, hv[k].x, d); d = fmaf(v[k].y, hv[k].y, d);
            d = fmaf(v[k].z, hv[k].z, d); d = fmaf(v[k].w, hv[k].w, d);
        }
        #pragma unroll
        for (int off = 16; off; off >>= 1) d += __shfl_xor_sync(0xffffffffu, d, off);
        if (lane == 0) g_scores[b*LSEQ + cch*128 + w*16 + i] = d;
        if (d > m){
            float sc = __expf(m - d);
            ssum *= sc;
            #pragma unroll
            for (int k = 0; k < 8; k++){
                ctx[k].x *= sc; ctx[k].y *= sc; ctx[k].z *= sc; ctx[k].w *= sc;
            }
            m = d;
        }
        float wg = __expf(d - m);
        ssum += wg;
        #pragma unroll
        for (int k = 0; k < 8; k++){
            ctx[k].x = fmaf(wg, v[k].x, ctx[k].x); ctx[k].y = fmaf(wg, v[k].y, ctx[k].y);
            ctx[k].z = fmaf(wg, v[k].z, ctx[k].z); ctx[k].w = fmaf(wg, v[k].w, ctx[k].w);
        }
    }

    if (lane == 0){ sm_m[w] = m; sm_s[w] = ssum; }
    __syncthreads();
    float mb = sm_m[0];
    #pragma unroll
    for (int jw = 1; jw < 8; jw++) mb = fmaxf(mb, sm_m[jw]);
    float sc = __expf(m - mb);
    #pragma unroll
    for (int k = 0; k < 8; k++){
        int e2 = (lane + 32*k)*4;
        cbuf[w*1024 + e2+0] = ctx[k].x*sc; cbuf[w*1024 + e2+1] = ctx[k].y*sc;
        cbuf[w*1024 + e2+2] = ctx[k].z*sc; cbuf[w*1024 + e2+3] = ctx[k].w*sc;
    }
    __syncthreads();
    for (int e2 = tid; e2 < 1024; e2 += 256){
        float s = 0.f;
        #pragma unroll
        for (int jw = 0; jw < 8; jw++) s += cbuf[jw*1024 + e2];
        g_pctx[(size_t)(b*16 + cch)*1024 + e2] = s;
    }
    if (tid == 0){
        float zb = 0.f;
        #pragma unroll
        for (int jw = 0; jw < 8; jw++) zb += sm_s[jw]*__expf(sm_m[jw] - mb);
        g_pm[b*16 + cch] = mb; g_ps[b*16 + cch] = zb;
    }
}

// ---------------- attention finalize ----------------
__global__ void attn_fin_k(float* __restrict__ out_attn)
{
    int b = blockIdx.x, tid = threadIdx.x;
    float M = -1e30f;
    #pragma unroll
    for (int cc = 0; cc < 16; cc++) M = fmaxf(M, g_pm[b*16 + cc]);
    float Z = 0.f;
    #pragma unroll
    for (int cc = 0; cc < 16; cc++) Z += g_ps[b*16 + cc]*__expf(g_pm[b*16 + cc] - M);
    float inv = 1.f / Z;
    for (int l = tid; l < LSEQ; l += 256)
        out_attn[b*LSEQ + l] = __expf(g_scores[b*LSEQ + l] - M) * inv;
    for (int e = tid; e < 1024; e += 256){
        float s = 0.f;
        #pragma unroll
        for (int cc = 0; cc < 16; cc++)
            s += __expf(g_pm[b*16 + cc] - M) * g_pctx[(size_t)(b*16 + cc)*1024 + e];
        float v = s * inv;
        __nv_bfloat16 hi, lo; split1(v, &hi, &lo);
        g_cathi[b*2048 + 1024 + e] = hi; g_catlo[b*2048 + 1024 + e] = lo;
    }
}

// ---------------- Wc combine ----------------
__global__ void cc_comb_k(const float* __restrict__ bc)
{
    int idx = blockIdx.x*256 + threadIdx.x;  // 65536
    int b = idx >> 10, n = idx & 1023;
    float s = bc[n];
    #pragma unroll
    for (int z = 0; z < 8; z++) s += g_ccpart[(size_t)(z*64 + b)*1024 + n];
    float v = tanhf(s);
    __nv_bfloat16 hi, lo; split1(v, &hi, &lo);
    g_cchi[idx] = hi; g_cclo[idx] = lo;
}

// ---------------- launch ----------------
extern "C" void kernel_launch(void* const* d_in, const int* in_sizes, int n_in,
                              void* d_out, int out_size)
{
    const int*   seq  = (const int*)d_in[0];
    const float* lh   = (const float*)d_in[1];
    const float* enc  = (const float*)d_in[2];
    const float* emb  = (const float*)d_in[3];
    const float* Wih0 = (const float*)d_in[4];
    const float* Whh0 = (const float*)d_in[5];
    const float* bih0 = (const float*)d_in[6];
    const float* bhh0 = (const float*)d_in[7];
    const float* Wih1 = (const float*)d_in[8];
    const float* Whh1 = (const float*)d_in[9];
    const float* bih1 = (const float*)d_in[10];
    const float* bhh1 = (const float*)d_in[11];
    const float* Wc   = (const float*)d_in[12];
    const float* bc   = (const float*)d_in[13];
    const float* Wout = (const float*)d_in[14];
    const float* bout = (const float*)d_in[15];

    float* out        = (float*)d_out;
    float* out_logits = out;                                   // [64, 32000]
    float* out_hidden = out + (size_t)BATCH*NVOC;              // [2, 64, 1024]
    float* out_attn   = out_hidden + 2*BATCH*HDIM;             // [64, 1, 2048]

    cudaFuncSetAttribute(gemm3_k, cudaFuncAttributeMaxDynamicSharedMemorySize, GSMEM3);
    cudaFuncSetAttribute(attn_pass_k, cudaFuncAttributeMaxDynamicSharedMemorySize, ASMEM);

    prep_k<<<768, 256>>>(seq, emb, lh);

    gemm3_k<<<dim3(24, 2, 4), 256, GSMEM3>>>(Wih0, Whh0, nullptr, nullptr, 1024, G3, 256, 0);
    gru_cell_k<<<256, 256>>>(bih0, bhh0, lh, out_hidden, 0);

    gemm3_k<<<dim3(24, 2, 4), 256, GSMEM3>>>(Wih1, Whh1, nullptr, nullptr, 1024, G3, 256, 1);
    gru_cell_k<<<256, 256>>>(bih1, bhh1, lh + BATCH*HDIM, out_hidden + BATCH*HDIM, 1);

    attn_pass_k<<<1024, 256, ASMEM>>>(enc);
    attn_fin_k<<<64, 256>>>(out_attn);

    gemm3_k<<<dim3(8, 1, 8), 256, GSMEM3>>>(Wc, nullptr, nullptr, nullptr, 2048, 1024, 256, 2);
    cc_comb_k<<<256, 256>>>(bc);

    gemm3_k<<<dim3(250, 1, 1), 256, GSMEM3>>>(Wout, nullptr, bout, out_logits, 1024, NVOC, 1024, 3);
}

// round 11
// speedup vs baseline: 1.1471x; 1.0790x over previous
#include <cuda_runtime.h>
#include <cuda_bf16.h>
#include <cuda_fp16.h>
#include <cstdint>

#define BATCH 64
#define HDIM  1024
#define LSEQ  2048
#define NVOC  32000
#define G3    3072

// ---------------- scratch (device globals; no allocation) ----------------
__device__ __nv_bfloat16 g_xhi[BATCH*HDIM],  g_xlo[BATCH*HDIM];
__device__ __nv_bfloat16 g_hphi[2*BATCH*HDIM], g_hplo[2*BATCH*HDIM];
__device__ __nv_bfloat16 g_h0hi[BATCH*HDIM], g_h0lo[BATCH*HDIM];
__device__ float         g_gpart[8*BATCH*G3];     // [y*4+z][64][3072]
__device__ float         g_h1[BATCH*HDIM];
__device__ __nv_bfloat16 g_cathi[BATCH*2*HDIM], g_catlo[BATCH*2*HDIM];
__device__ float         g_scores[BATCH*LSEQ];
__device__ float         g_pm[BATCH*16], g_ps[BATCH*16];
__device__ float         g_pctx[BATCH*16*HDIM];
__device__ float         g_ccpart[8*BATCH*HDIM]; // [z][64][1024]
__device__ __half        g_cc16[BATCH*HDIM];

// ---------------- helpers ----------------
__device__ __forceinline__ uint32_t pk_hi(float x, float y){
    return (__float_as_uint(x) >> 16) | (__float_as_uint(y) & 0xffff0000u);
}
__device__ __forceinline__ uint32_t pk_lo(float x, float y){
    float rx = x - __uint_as_float(__float_as_uint(x) & 0xffff0000u);
    float ry = y - __uint_as_float(__float_as_uint(y) & 0xffff0000u);
    return (__float_as_uint(rx) >> 16) | (__float_as_uint(ry) & 0xffff0000u);
}
__device__ __forceinline__ void split1(float v, __nv_bfloat16* hi, __nv_bfloat16* lo){
    uint32_t u  = __float_as_uint(v);
    uint32_t uh = u & 0xffff0000u;
    float r = v - __uint_as_float(uh);
    *hi = __ushort_as_bfloat16((unsigned short)(uh >> 16));
    *lo = __ushort_as_bfloat16((unsigned short)(__float_as_uint(r) >> 16));
}
__device__ __forceinline__ void mma16816(float* c, const uint32_t* a, uint32_t b0, uint32_t b1){
    asm volatile("mma.sync.aligned.m16n8k16.row.col.f32.bf16.bf16.f32 "
        "{%0,%1,%2,%3}, {%4,%5,%6,%7}, {%8,%9}, {%0,%1,%2,%3};"
        : "+f"(c[0]), "+f"(c[1]), "+f"(c[2]), "+f"(c[3])
        : "r"(a[0]), "r"(a[1]), "r"(a[2]), "r"(a[3]), "r"(b0), "r"(b1));
}
__device__ __forceinline__ void mma16816h(float* c, const uint32_t* a, uint32_t b0, uint32_t b1){
    asm volatile("mma.sync.aligned.m16n8k16.row.col.f32.f16.f16.f32 "
        "{%0,%1,%2,%3}, {%4,%5,%6,%7}, {%8,%9}, {%0,%1,%2,%3};"
        : "+f"(c[0]), "+f"(c[1]), "+f"(c[2]), "+f"(c[3])
        : "r"(a[0]), "r"(a[1]), "r"(a[2]), "r"(a[3]), "r"(b0), "r"(b1));
}
__device__ __forceinline__ void ldsm4(uint32_t* d, uint32_t saddr){
    asm volatile("ldmatrix.sync.aligned.m8n8.x4.shared.b16 {%0,%1,%2,%3}, [%4];"
        : "=r"(d[0]), "=r"(d[1]), "=r"(d[2]), "=r"(d[3]) : "r"(saddr));
}
__device__ __forceinline__ void cp16(void* sdst, const void* gsrc){
    uint32_t s = (uint32_t)__cvta_generic_to_shared(sdst);
    asm volatile("cp.async.cg.shared.global [%0], [%1], 16;" :: "r"(s), "l"(gsrc));
}
__device__ __forceinline__ uint32_t h2_pack(float x, float y){
    uint32_t u;
    asm("cvt.rn.f16x2.f32 %0, %1, %2;" : "=r"(u) : "f"(y), "f"(x));  // y->hi, x->lo
    return u;
}

// ---------------- prep: embed gather + hi/lo split of x and h_prev ----------------
__global__ void prep_k(const int* __restrict__ seq, const float* __restrict__ embed,
                       const float* __restrict__ lh)
{
    int idx = blockIdx.x*256 + threadIdx.x;     // 3 * 65536
    int z = idx >> 16, r = idx & 65535;
    float v;
    if (z == 0){
        int b = r >> 10, j = r & 1023;
        v = embed[(size_t)seq[b]*HDIM + j];
    } else {
        v = lh[(size_t)(z-1)*BATCH*HDIM + r];
    }
    __nv_bfloat16 hi, lo; split1(v, &hi, &lo);
    if (z == 0){ g_xhi[r] = hi; g_xlo[r] = lo; }
    else       { g_hphi[(z-1)*BATCH*HDIM + r] = hi; g_hplo[(z-1)*BATCH*HDIM + r] = lo; }
}

// ---------------- gemm3: bf16 3-term split (GRU + Wc) ----------------
// out = act(64xK) @ W(NxK)^T over K-range [zz*KS, (zz+1)*KS)
// mode 0/1: GRU layer 0/1 -> g_gpart   mode 2: Wc -> g_ccpart
#define GSMEM3 110592
__global__ void __launch_bounds__(256, 2)
gemm3_k(const float* __restrict__ W0, const float* __restrict__ W1,
        int K, int N, int KS, int mode)
{
    extern __shared__ char sraw[];
    uint32_t sb = (uint32_t)__cvta_generic_to_shared(sraw);

    int y = blockIdx.y, zz = blockIdx.z;
    const float* W = y ? W1 : W0;
    const __nv_bfloat16 *Ahp, *Alp;
    float* op;
    if (mode == 0){ Ahp = y ? g_hphi : g_xhi;  Alp = y ? g_hplo : g_xlo;  op = g_gpart; }
    else if (mode == 1){
        Ahp = y ? (g_hphi + BATCH*HDIM) : g_h0hi;
        Alp = y ? (g_hplo + BATCH*HDIM) : g_h0lo;  op = g_gpart;
    } else { Ahp = g_cathi; Alp = g_catlo; op = g_ccpart; }
    const uint32_t* Agh = (const uint32_t*)Ahp;
    const uint32_t* Agl = (const uint32_t*)Alp;

    int tid = threadIdx.x, w = tid >> 5, lane = tid & 31;
    int r = lane >> 2, c = lane & 3;
    int nblk = blockIdx.x * 128;
    int K2 = K >> 1;
    int kbeg = zz * KS;
    int nchunk = KS >> 5;
    int nsec = KS >> 7;

    uint32_t aoff = (uint32_t)((lane & 15)*272 + (lane >> 4)*16);
    const float* Wwarp = W + (size_t)(nblk + w*16)*K;

    auto loadA = [&](int s, int b){
        int ku = (kbeg + s*128) >> 1;
        #pragma unroll
        for (int i = 0; i < 4; i++){
            int p = tid + i*256;
            int row = p >> 4, c16 = p & 15;
            const uint32_t* sh = Agh + (size_t)row*K2 + ku + c16*4;
            const uint32_t* sl = Agl + (size_t)row*K2 + ku + c16*4;
            cp16(sraw + b*34816 + row*272 + c16*16, sh);
            cp16(sraw + b*34816 + 17408 + row*272 + c16*16, sl);
        }
    };
    auto issueW = [&](int g, int st){
        int kco = kbeg + g*32;
        char* wd = sraw + 69632 + w*5120 + st*2560;
        #pragma unroll
        for (int j = 0; j < 4; j++){
            int q = lane + j*32;
            int row = q >> 3, c8 = q & 7;
            cp16(wd + row*160 + c8*16, Wwarp + (size_t)row*K + kco + c8*4);
        }
    };

    float acc[4][2][4];
    #pragma unroll
    for (int i=0;i<4;i++)
        #pragma unroll
        for (int j=0;j<2;j++)
            #pragma unroll
            for (int q=0;q<4;q++) acc[i][j][q] = 0.f;

    loadA(0, 0);
    issueW(0, 0);
    asm volatile("cp.async.commit_group;");
    issueW(1, 1);
    asm volatile("cp.async.commit_group;");

    for (int g = 0; g < nchunk; g++){
        if (g == nchunk - 1) asm volatile("cp.async.wait_group 0;");
        else                 asm volatile("cp.async.wait_group 1;");
        __syncwarp();
        if ((g & 3) == 0) __syncthreads();

        {
            int bufA = (g >> 2) & 1;
            uint32_t cloc = (uint32_t)((g & 3) * 64);
            uint32_t aHb = sb + bufA*34816 + aoff + cloc;
            uint32_t aLb = aHb + 17408;
            const float2* wst = (const float2*)(sraw + 69632 + w*5120 + (g & 1)*2560);

            #pragma unroll
            for (int ki = 0; ki < 2; ki++){
                uint32_t bh[2][2], bl[2][2];
                #pragma unroll
                for (int nt = 0; nt < 2; nt++){
                    int nl = nt*8 + r;
                    const float2* wp = wst + nl*20 + ki*8 + c;
                    float2 w0 = wp[0], w1 = wp[4];
                    bh[nt][0] = pk_hi(w0.x, w0.y);  bl[nt][0] = pk_lo(w0.x, w0.y);
                    bh[nt][1] = pk_hi(w1.x, w1.y);  bl[nt][1] = pk_lo(w1.x, w1.y);
                }
                #pragma unroll
                for (int mt = 0; mt < 4; mt++){
                    uint32_t ah[4], aw[4];
                    ldsm4(ah, aHb + mt*4352 + ki*32);
                    ldsm4(aw, aLb + mt*4352 + ki*32);
                    #pragma unroll
                    for (int nt = 0; nt < 2; nt++){
                        mma16816(acc[mt][nt], ah, bh[nt][0], bh[nt][1]);
                        mma16816(acc[mt][nt], aw, bh[nt][0], bh[nt][1]);
                        mma16816(acc[mt][nt], ah, bl[nt][0], bl[nt][1]);
                    }
                }
            }
        }

        bool did = false;
        if ((g & 3) == 0 && (g >> 2) + 1 < nsec){
            loadA((g >> 2) + 1, ((g >> 2) + 1) & 1);
            did = true;
        }
        if (g + 2 < nchunk){
            issueW(g + 2, (g + 2) & 1);
            did = true;
        }
        if (did) asm volatile("cp.async.commit_group;");
    }

    int nw = nblk + w*16, cq = c*2;
    float* o = op + (size_t)((y*gridDim.z + zz) * 64) * N;
    #pragma unroll
    for (int mt = 0; mt < 4; mt++)
        #pragma unroll
        for (int nt = 0; nt < 2; nt++){
            int row = mt*16 + r, col = nw + nt*8 + cq;
            *(float2*)(o + (size_t)row*N + col)     = make_float2(acc[mt][nt][0], acc[mt][nt][1]);
            *(float2*)(o + (size_t)(row+8)*N + col) = make_float2(acc[mt][nt][2], acc[mt][nt][3]);
        }
}

// ---------------- wout16: single-term fp16 GEMM for logits ----------------
// out(64x32000) = cc16(64x1024) @ Wout(32000x1024)^T + bias. K=1024 full per CTA.
// SMEM: A [2][64 rows][272B] @ 0 / 17408 ; W @ 34816 + w*5120 + st*2560 (stride 160B)
#define WSMEM 75776
__global__ void __launch_bounds__(256, 2)
wout16_k(const float* __restrict__ W, const float* __restrict__ bias,
         float* __restrict__ out)
{
    extern __shared__ char sraw[];
    uint32_t sb = (uint32_t)__cvta_generic_to_shared(sraw);
    const int K = 1024, N = NVOC;

    int tid = threadIdx.x, w = tid >> 5, lane = tid & 31;
    int r = lane >> 2, c = lane & 3;
    int nblk = blockIdx.x * 128;

    uint32_t aoff = (uint32_t)((lane & 15)*272 + (lane >> 4)*16);
    const float* Wwarp = W + (size_t)(nblk + w*16)*K;
    const __half* A = g_cc16;

    auto loadA = [&](int s, int b){
        #pragma unroll
        for (int i = 0; i < 4; i++){
            int p = tid + i*256;            // 0..1023
            int row = p >> 4, c16 = p & 15;
            cp16(sraw + b*17408 + row*272 + c16*16, A + (size_t)row*K + s*128 + c16*8);
        }
    };
    auto issueW = [&](int g, int st){
        int kco = g*32;
        char* wd = sraw + 34816 + w*5120 + st*2560;
        #pragma unroll
        for (int j = 0; j < 4; j++){
            int q = lane + j*32;
            int row = q >> 3, c8 = q & 7;
            cp16(wd + row*160 + c8*16, Wwarp + (size_t)row*K + kco + c8*4);
        }
    };

    float acc[4][2][4];
    #pragma unroll
    for (int i=0;i<4;i++)
        #pragma unroll
        for (int j=0;j<2;j++)
            #pragma unroll
            for (int q=0;q<4;q++) acc[i][j][q] = 0.f;

    loadA(0, 0);
    issueW(0, 0);
    asm volatile("cp.async.commit_group;");
    issueW(1, 1);
    asm volatile("cp.async.commit_group;");

    const int nchunk = 32, nsec = 8;
    for (int g = 0; g < nchunk; g++){
        if (g == nchunk - 1) asm volatile("cp.async.wait_group 0;");
        else                 asm volatile("cp.async.wait_group 1;");
        __syncwarp();
        if ((g & 3) == 0) __syncthreads();

        {
            int bufA = (g >> 2) & 1;
            uint32_t aHb = sb + bufA*17408 + aoff + (uint32_t)((g & 3) * 64);
            const float2* wst = (const float2*)(sraw + 34816 + w*5120 + (g & 1)*2560);

            #pragma unroll
            for (int ki = 0; ki < 2; ki++){
                uint32_t bh[2][2];
                #pragma unroll
                for (int nt = 0; nt < 2; nt++){
                    int nl = nt*8 + r;
                    const float2* wp = wst + nl*20 + ki*8 + c;
                    float2 w0 = wp[0], w1 = wp[4];
                    bh[nt][0] = h2_pack(w0.x, w0.y);
                    bh[nt][1] = h2_pack(w1.x, w1.y);
                }
                #pragma unroll
                for (int mt = 0; mt < 4; mt++){
                    uint32_t ah[4];
                    ldsm4(ah, aHb + mt*4352 + ki*32);
                    mma16816h(acc[mt][0], ah, bh[0][0], bh[0][1]);
                    mma16816h(acc[mt][1], ah, bh[1][0], bh[1][1]);
                }
            }
        }

        bool did = false;
        if ((g & 3) == 0 && (g >> 2) + 1 < nsec){
            loadA((g >> 2) + 1, ((g >> 2) + 1) & 1);
            did = true;
        }
        if (g + 2 < nchunk){
            issueW(g + 2, (g + 2) & 1);
            did = true;
        }
        if (did) asm volatile("cp.async.commit_group;");
    }

    int nw = nblk + w*16, cq = c*2;
    #pragma unroll
    for (int mt = 0; mt < 4; mt++)
        #pragma unroll
        for (int nt = 0; nt < 2; nt++){
            int row = mt*16 + r, col = nw + nt*8 + cq;
            float2 bb = *(const float2*)(bias + col);
            *(float2*)(out + (size_t)row*N + col)     = make_float2(acc[mt][nt][0] + bb.x, acc[mt][nt][1] + bb.y);
            *(float2*)(out + (size_t)(row+8)*N + col) = make_float2(acc[mt][nt][2] + bb.x, acc[mt][nt][3] + bb.y);
        }
}

// ---------------- GRU elementwise cell (4 split-K partials) ----------------
__global__ void gru_cell_k(const float* __restrict__ bi, const float* __restrict__ bh,
                           const float* __restrict__ hprev, float* __restrict__ hout,
                           int layer)
{
    int idx = blockIdx.x*256 + threadIdx.x;   // 65536
    int b = idx >> 10, j = idx & 1023;
    float xr=0.f, xz=0.f, xn=0.f, hr=0.f, hz=0.f, hn=0.f;
    #pragma unroll
    for (int ks = 0; ks < 4; ks++){
        const float* gi = g_gpart + (size_t)(ks*64 + b)*G3;
        const float* gh = g_gpart + (size_t)((4+ks)*64 + b)*G3;
        xr += gi[j]; xz += gi[1024+j]; xn += gi[2048+j];
        hr += gh[j]; hz += gh[1024+j]; hn += gh[2048+j];
    }
    xr += bi[j]; xz += bi[1024+j]; xn += bi[2048+j];
    hr += bh[j]; hz += bh[1024+j]; hn += bh[2048+j];
    float rr = 1.f/(1.f + expf(-(xr+hr)));
    float zg = 1.f/(1.f + expf(-(xz+hz)));
    float nn = tanhf(xn + rr*hn);
    float h  = (1.f - zg)*nn + zg*hprev[idx];
    hout[idx] = h;
    __nv_bfloat16 hi, lo; split1(h, &hi, &lo);
    if (layer == 0){ g_h0hi[idx] = hi; g_h0lo[idx] = lo; }
    else { g_cathi[b*2048 + j] = hi; g_catlo[b*2048 + j] = lo; g_h1[idx] = h; }
}

// ---------------- attention pass 1: cp.async row double-buffer, online softmax ----------------
#define ASMEM 69760
__global__ void __launch_bounds__(256, 2) attn_pass_k(const float* __restrict__ enc)
{
    extern __shared__ char araw[];
    float* sbuf = (float*)araw;                 // [8 warps][2][1024]
    float* cbuf = sbuf;                         // alias after main loop
    float* smhv = (float*)(araw + 65536);       // [1024]
    float* sm_m = smhv + 1024;
    float* sm_s = sm_m + 8;

    int b = blockIdx.x >> 4, cch = blockIdx.x & 15;
    int tid = threadIdx.x, w = tid >> 5, lane = tid & 31;

    for (int i = tid; i < 1024; i += 256) smhv[i] = g_h1[b*1024 + i];
    __syncthreads();
    float4 hv[8];
    #pragma unroll
    for (int k = 0; k < 8; k++) hv[k] = ((const float4*)smhv)[lane + 32*k];
    float4 ctx[8];
    #pragma unroll
    for (int k = 0; k < 8; k++) ctx[k] = make_float4(0.f,0.f,0.f,0.f);
    float m = -1e30f, ssum = 0.f;

    const float* ebase = enc + ((size_t)b*LSEQ + cch*128 + w*16)*1024;
    float* mybuf = sbuf + w*2048;

    #pragma unroll
    for (int s = 0; s < 8; s++)
        cp16(mybuf + lane*4 + s*128, ebase + lane*4 + s*128);
    asm volatile("cp.async.commit_group;");

    for (int i = 0; i < 16; i++){
        if (i < 15){
            const float* src = ebase + (size_t)(i+1)*1024;
            float* dst = mybuf + ((i+1)&1)*1024;
            #pragma unroll
            for (int s = 0; s < 8; s++)
                cp16(dst + lane*4 + s*128, src + lane*4 + s*128);
            asm volatile("cp.async.commit_group;");
            asm volatile("cp.async.wait_group 1;");
        } else {
            asm volatile("cp.async.wait_group 0;");
        }
        const float4* v4 = (const float4*)(mybuf + (i&1)*1024);
        float4 v[8];
        #pragma unroll
        for (int k = 0; k < 8; k++) v[k] = v4[lane + 32*k];
        float d = 0.f;
        #pragma unroll
        for (int k = 0; k < 8; k++){
            d = fmaf(v[k].x, hv[k].x, d); d = fmaf(v[k].y, hv[k].y, d);
            d = fmaf(v[k].z, hv[k].z, d); d = fmaf(v[k].w, hv[k].w, d);
        }
        #pragma unroll
        for (int off = 16; off; off >>= 1) d += __shfl_xor_sync(0xffffffffu, d, off);
        if (lane == 0) g_scores[b*LSEQ + cch*128 + w*16 + i] = d;
        if (d > m){
            float sc = __expf(m - d);
            ssum *= sc;
            #pragma unroll
            for (int k = 0; k < 8; k++){
                ctx[k].x *= sc; ctx[k].y *= sc; ctx[k].z *= sc; ctx[k].w *= sc;
            }
            m = d;
        }
        float wg = __expf(d - m);
        ssum += wg;
        #pragma unroll
        for (int k = 0; k < 8; k++){
            ctx[k].x = fmaf(wg, v[k].x, ctx[k].x); ctx[k].y = fmaf(wg, v[k].y, ctx[k].y);
            ctx[k].z = fmaf(wg, v[k].z, ctx[k].z); ctx[k].w = fmaf(wg, v[k].w, ctx[k].w);
        }
    }

    if (lane == 0){ sm_m[w] = m; sm_s[w] = ssum; }
    __syncthreads();
    float mb = sm_m[0];
    #pragma unroll
    for (int jw = 1; jw < 8; jw++) mb = fmaxf(mb, sm_m[jw]);
    float sc = __expf(m - mb);
    #pragma unroll
    for (int k = 0; k < 8; k++){
        int e2 = (lane + 32*k)*4;
        cbuf[w*1024 + e2+0] = ctx[k].x*sc; cbuf[w*1024 + e2+1] = ctx[k].y*sc;
        cbuf[w*1024 + e2+2] = ctx[k].z*sc; cbuf[w*1024 + e2+3] = ctx[k].w*sc;
    }
    __syncthreads();
    for (int e2 = tid; e2 < 1024; e2 += 256){
        float s = 0.f;
        #pragma unroll
        for (int jw = 0; jw < 8; jw++) s += cbuf[jw*1024 + e2];
        g_pctx[(size_t)(b*16 + cch)*1024 + e2] = s;
    }
    if (tid == 0){
        float zb = 0.f;
        #pragma unroll
        for (int jw = 0; jw < 8; jw++) zb += sm_s[jw]*__expf(sm_m[jw] - mb);
        g_pm[b*16 + cch] = mb; g_ps[b*16 + cch] = zb;
    }
}

// ---------------- attention finalize ----------------
__global__ void attn_fin_k(float* __restrict__ out_attn)
{
    int b = blockIdx.x, tid = threadIdx.x;
    float M = -1e30f;
    #pragma unroll
    for (int cc = 0; cc < 16; cc++) M = fmaxf(M, g_pm[b*16 + cc]);
    float Z = 0.f;
    #pragma unroll
    for (int cc = 0; cc < 16; cc++) Z += g_ps[b*16 + cc]*__expf(g_pm[b*16 + cc] - M);
    float inv = 1.f / Z;
    for (int l = tid; l < LSEQ; l += 256)
        out_attn[b*LSEQ + l] = __expf(g_scores[b*LSEQ + l] - M) * inv;
    for (int e = tid; e < 1024; e += 256){
        float s = 0.f;
        #pragma unroll
        for (int cc = 0; cc < 16; cc++)
            s += __expf(g_pm[b*16 + cc] - M) * g_pctx[(size_t)(b*16 + cc)*1024 + e];
        float v = s * inv;
        __nv_bfloat16 hi, lo; split1(v, &hi, &lo);
        g_cathi[b*2048 + 1024 + e] = hi; g_catlo[b*2048 + 1024 + e] = lo;
    }
}

// ---------------- Wc combine: partials + bias + tanh -> fp16 cc ----------------
__global__ void cc_comb_k(const float* __restrict__ bc)
{
    int idx = blockIdx.x*256 + threadIdx.x;  // 65536
    int b = idx >> 10, n = idx & 1023;
    float s = bc[n];
    #pragma unroll
    for (int z = 0; z < 8; z++) s += g_ccpart[(size_t)(z*64 + b)*1024 + n];
    g_cc16[idx] = __float2half_rn(tanhf(s));
}

// ---------------- launch ----------------
extern "C" void kernel_launch(void* const* d_in, const int* in_sizes, int n_in,
                              void* d_out, int out_size)
{
    const int*   seq  = (const int*)d_in[0];
    const float* lh   = (const float*)d_in[1];
    const float* enc  = (const float*)d_in[2];
    const float* emb  = (const float*)d_in[3];
    const float* Wih0 = (const float*)d_in[4];
    const float* Whh0 = (const float*)d_in[5];
    const float* bih0 = (const float*)d_in[6];
    const float* bhh0 = (const float*)d_in[7];
    const float* Wih1 = (const float*)d_in[8];
    const float* Whh1 = (const float*)d_in[9];
    const float* bih1 = (const float*)d_in[10];
    const float* bhh1 = (const float*)d_in[11];
    const float* Wc   = (const float*)d_in[12];
    const float* bc   = (const float*)d_in[13];
    const float* Wout = (const float*)d_in[14];
    const float* bout = (const float*)d_in[15];

    float* out        = (float*)d_out;
    float* out_logits = out;                                   // [64, 32000]
    float* out_hidden = out + (size_t)BATCH*NVOC;              // [2, 64, 1024]
    float* out_attn   = out_hidden + 2*BATCH*HDIM;             // [64, 1, 2048]

    cudaFuncSetAttribute(gemm3_k, cudaFuncAttributeMaxDynamicSharedMemorySize, GSMEM3);
    cudaFuncSetAttribute(wout16_k, cudaFuncAttributeMaxDynamicSharedMemorySize, WSMEM);
    cudaFuncSetAttribute(attn_pass_k, cudaFuncAttributeMaxDynamicSharedMemorySize, ASMEM);

    prep_k<<<768, 256>>>(seq, emb, lh);

    gemm3_k<<<dim3(24, 2, 4), 256, GSMEM3>>>(Wih0, Whh0, 1024, G3, 256, 0);
    gru_cell_k<<<256, 256>>>(bih0, bhh0, lh, out_hidden, 0);

    gemm3_k<<<dim3(24, 2, 4), 256, GSMEM3>>>(Wih1, Whh1, 1024, G3, 256, 1);
    gru_cell_k<<<256, 256>>>(bih1, bhh1, lh + BATCH*HDIM, out_hidden + BATCH*HDIM, 1);

    attn_pass_k<<<1024, 256, ASMEM>>>(enc);
    attn_fin_k<<<64, 256>>>(out_attn);

    gemm3_k<<<dim3(8, 1, 8), 256, GSMEM3>>>(Wc, nullptr, 2048, 1024, 256, 2);
    cc_comb_k<<<256, 256>>>(bc);

    wout16_k<<<250, 256, WSMEM>>>(Wout, bout, out_logits);
}

// round 12
// speedup vs baseline: 1.1754x; 1.0246x over previous
#include <cuda_runtime.h>
#include <cuda_bf16.h>
#include <cuda_fp16.h>
#include <cstdint>

#define BATCH 64
#define HDIM  1024
#define LSEQ  2048
#define NVOC  32000
#define G3    3072

// ---------------- scratch (device globals; no allocation) ----------------
__device__ __nv_bfloat16 g_xhi[BATCH*HDIM],  g_xlo[BATCH*HDIM];
__device__ __nv_bfloat16 g_hphi[2*BATCH*HDIM], g_hplo[2*BATCH*HDIM];
__device__ __nv_bfloat16 g_h0hi[BATCH*HDIM], g_h0lo[BATCH*HDIM];
__device__ float         g_gpart[16*BATCH*G3];    // [y*8+z][64][3072]
__device__ float         g_h1[BATCH*HDIM];
__device__ __half        g_cat16[BATCH*2*HDIM];
__device__ float         g_scores[BATCH*LSEQ];
__device__ float         g_pm[BATCH*16], g_ps[BATCH*16];
__device__ float         g_pctx[BATCH*16*HDIM];
__device__ float         g_ccpart[16*BATCH*HDIM]; // [z][64][1024]
__device__ __half        g_cc16[BATCH*HDIM];

// ---------------- helpers ----------------
__device__ __forceinline__ uint32_t pk_hi(float x, float y){
    return (__float_as_uint(x) >> 16) | (__float_as_uint(y) & 0xffff0000u);
}
__device__ __forceinline__ uint32_t pk_lo(float x, float y){
    float rx = x - __uint_as_float(__float_as_uint(x) & 0xffff0000u);
    float ry = y - __uint_as_float(__float_as_uint(y) & 0xffff0000u);
    return (__float_as_uint(rx) >> 16) | (__float_as_uint(ry) & 0xffff0000u);
}
__device__ __forceinline__ void split1(float v, __nv_bfloat16* hi, __nv_bfloat16* lo){
    uint32_t u  = __float_as_uint(v);
    uint32_t uh = u & 0xffff0000u;
    float r = v - __uint_as_float(uh);
    *hi = __ushort_as_bfloat16((unsigned short)(uh >> 16));
    *lo = __ushort_as_bfloat16((unsigned short)(__float_as_uint(r) >> 16));
}
__device__ __forceinline__ void mma16816(float* c, const uint32_t* a, uint32_t b0, uint32_t b1){
    asm volatile("mma.sync.aligned.m16n8k16.row.col.f32.bf16.bf16.f32 "
        "{%0,%1,%2,%3}, {%4,%5,%6,%7}, {%8,%9}, {%0,%1,%2,%3};"
        : "+f"(c[0]), "+f"(c[1]), "+f"(c[2]), "+f"(c[3])
        : "r"(a[0]), "r"(a[1]), "r"(a[2]), "r"(a[3]), "r"(b0), "r"(b1));
}
__device__ __forceinline__ void mma16816h(float* c, const uint32_t* a, uint32_t b0, uint32_t b1){
    asm volatile("mma.sync.aligned.m16n8k16.row.col.f32.f16.f16.f32 "
        "{%0,%1,%2,%3}, {%4,%5,%6,%7}, {%8,%9}, {%0,%1,%2,%3};"
        : "+f"(c[0]), "+f"(c[1]), "+f"(c[2]), "+f"(c[3])
        : "r"(a[0]), "r"(a[1]), "r"(a[2]), "r"(a[3]), "r"(b0), "r"(b1));
}
__device__ __forceinline__ void ldsm4(uint32_t* d, uint32_t saddr){
    asm volatile("ldmatrix.sync.aligned.m8n8.x4.shared.b16 {%0,%1,%2,%3}, [%4];"
        : "=r"(d[0]), "=r"(d[1]), "=r"(d[2]), "=r"(d[3]) : "r"(saddr));
}
__device__ __forceinline__ void cp16(void* sdst, const void* gsrc){
    uint32_t s = (uint32_t)__cvta_generic_to_shared(sdst);
    asm volatile("cp.async.cg.shared.global [%0], [%1], 16;" :: "r"(s), "l"(gsrc));
}
__device__ __forceinline__ uint32_t h2_pack(float x, float y){
    uint32_t u;
    asm("cvt.rn.f16x2.f32 %0, %1, %2;" : "=r"(u) : "f"(y), "f"(x));  // y->hi, x->lo
    return u;
}

// ---------------- prep: embed gather + hi/lo split of x and h_prev ----------------
__global__ void prep_k(const int* __restrict__ seq, const float* __restrict__ embed,
                       const float* __restrict__ lh)
{
    int idx = blockIdx.x*256 + threadIdx.x;     // 3 * 65536
    int z = idx >> 16, r = idx & 65535;
    float v;
    if (z == 0){
        int b = r >> 10, j = r & 1023;
        v = embed[(size_t)seq[b]*HDIM + j];
    } else {
        v = lh[(size_t)(z-1)*BATCH*HDIM + r];
    }
    __nv_bfloat16 hi, lo; split1(v, &hi, &lo);
    if (z == 0){ g_xhi[r] = hi; g_xlo[r] = lo; }
    else       { g_hphi[(z-1)*BATCH*HDIM + r] = hi; g_hplo[(z-1)*BATCH*HDIM + r] = lo; }
}

// ---------------- gemm3: bf16 3-term split (GRU only) ----------------
// partial = act(64xK) @ W(NxK)^T over K-range [zz*KS, (zz+1)*KS)  -> g_gpart[y*gridDim.z+zz]
#define GSMEM3 110592
__global__ void __launch_bounds__(256, 2)
gemm3_k(const float* __restrict__ W0, const float* __restrict__ W1,
        int K, int N, int KS, int mode)
{
    extern __shared__ char sraw[];
    uint32_t sb = (uint32_t)__cvta_generic_to_shared(sraw);

    int y = blockIdx.y, zz = blockIdx.z;
    const float* W = y ? W1 : W0;
    const __nv_bfloat16 *Ahp, *Alp;
    if (mode == 0){ Ahp = y ? g_hphi : g_xhi;  Alp = y ? g_hplo : g_xlo; }
    else {
        Ahp = y ? (g_hphi + BATCH*HDIM) : g_h0hi;
        Alp = y ? (g_hplo + BATCH*HDIM) : g_h0lo;
    }
    float* op = g_gpart;
    const uint32_t* Agh = (const uint32_t*)Ahp;
    const uint32_t* Agl = (const uint32_t*)Alp;

    int tid = threadIdx.x, w = tid >> 5, lane = tid & 31;
    int r = lane >> 2, c = lane & 3;
    int nblk = blockIdx.x * 128;
    int K2 = K >> 1;
    int kbeg = zz * KS;
    int nchunk = KS >> 5;
    int nsec = KS >> 7;

    uint32_t aoff = (uint32_t)((lane & 15)*272 + (lane >> 4)*16);
    const float* Wwarp = W + (size_t)(nblk + w*16)*K;

    auto loadA = [&](int s, int b){
        int ku = (kbeg + s*128) >> 1;
        #pragma unroll
        for (int i = 0; i < 4; i++){
            int p = tid + i*256;
            int row = p >> 4, c16 = p & 15;
            const uint32_t* sh = Agh + (size_t)row*K2 + ku + c16*4;
            const uint32_t* sl = Agl + (size_t)row*K2 + ku + c16*4;
            cp16(sraw + b*34816 + row*272 + c16*16, sh);
            cp16(sraw + b*34816 + 17408 + row*272 + c16*16, sl);
        }
    };
    auto issueW = [&](int g, int st){
        int kco = kbeg + g*32;
        char* wd = sraw + 69632 + w*5120 + st*2560;
        #pragma unroll
        for (int j = 0; j < 4; j++){
            int q = lane + j*32;
            int row = q >> 3, c8 = q & 7;
            cp16(wd + row*160 + c8*16, Wwarp + (size_t)row*K + kco + c8*4);
        }
    };

    float acc[4][2][4];
    #pragma unroll
    for (int i=0;i<4;i++)
        #pragma unroll
        for (int j=0;j<2;j++)
            #pragma unroll
            for (int q=0;q<4;q++) acc[i][j][q] = 0.f;

    loadA(0, 0);
    issueW(0, 0);
    asm volatile("cp.async.commit_group;");
    issueW(1, 1);
    asm volatile("cp.async.commit_group;");

    for (int g = 0; g < nchunk; g++){
        if (g == nchunk - 1) asm volatile("cp.async.wait_group 0;");
        else                 asm volatile("cp.async.wait_group 1;");
        __syncwarp();
        if ((g & 3) == 0) __syncthreads();

        {
            int bufA = (g >> 2) & 1;
            uint32_t cloc = (uint32_t)((g & 3) * 64);
            uint32_t aHb = sb + bufA*34816 + aoff + cloc;
            uint32_t aLb = aHb + 17408;
            const float2* wst = (const float2*)(sraw + 69632 + w*5120 + (g & 1)*2560);

            #pragma unroll
            for (int ki = 0; ki < 2; ki++){
                uint32_t bh[2][2], bl[2][2];
                #pragma unroll
                for (int nt = 0; nt < 2; nt++){
                    int nl = nt*8 + r;
                    const float2* wp = wst + nl*20 + ki*8 + c;
                    float2 w0 = wp[0], w1 = wp[4];
                    bh[nt][0] = pk_hi(w0.x, w0.y);  bl[nt][0] = pk_lo(w0.x, w0.y);
                    bh[nt][1] = pk_hi(w1.x, w1.y);  bl[nt][1] = pk_lo(w1.x, w1.y);
                }
                #pragma unroll
                for (int mt = 0; mt < 4; mt++){
                    uint32_t ah[4], aw[4];
                    ldsm4(ah, aHb + mt*4352 + ki*32);
                    ldsm4(aw, aLb + mt*4352 + ki*32);
                    #pragma unroll
                    for (int nt = 0; nt < 2; nt++){
                        mma16816(acc[mt][nt], ah, bh[nt][0], bh[nt][1]);
                        mma16816(acc[mt][nt], aw, bh[nt][0], bh[nt][1]);
                        mma16816(acc[mt][nt], ah, bl[nt][0], bl[nt][1]);
                    }
                }
            }
        }

        bool did = false;
        if ((g & 3) == 0 && (g >> 2) + 1 < nsec){
            loadA((g >> 2) + 1, ((g >> 2) + 1) & 1);
            did = true;
        }
        if (g + 2 < nchunk){
            issueW(g + 2, (g + 2) & 1);
            did = true;
        }
        if (did) asm volatile("cp.async.commit_group;");
    }

    int nw = nblk + w*16, cq = c*2;
    float* o = op + (size_t)((y*gridDim.z + zz) * 64) * N;
    #pragma unroll
    for (int mt = 0; mt < 4; mt++)
        #pragma unroll
        for (int nt = 0; nt < 2; nt++){
            int row = mt*16 + r, col = nw + nt*8 + cq;
            *(float2*)(o + (size_t)row*N + col)     = make_float2(acc[mt][nt][0], acc[mt][nt][1]);
            *(float2*)(o + (size_t)(row+8)*N + col) = make_float2(acc[mt][nt][2], acc[mt][nt][3]);
        }
}

// ---------------- gemm16: single-term fp16 GEMM (Wc partials + Wout direct) ----------------
// mode 0: partial -> outp[(zz*64+row)*N]   mode 1: direct + bias -> outp[row*N]
#define WSMEM 75776
__global__ void __launch_bounds__(256, 2)
gemm16_k(const __half* __restrict__ A, const float* __restrict__ W,
         const float* __restrict__ bias, float* __restrict__ outp,
         int K, int N, int KS, int mode)
{
    extern __shared__ char sraw[];
    uint32_t sb = (uint32_t)__cvta_generic_to_shared(sraw);

    int tid = threadIdx.x, w = tid >> 5, lane = tid & 31;
    int r = lane >> 2, c = lane & 3;
    int nblk = blockIdx.x * 128;
    int zz = blockIdx.z;
    int kbeg = zz * KS;
    int nchunk = KS >> 5;
    int nsec = KS >> 7;

    uint32_t aoff = (uint32_t)((lane & 15)*272 + (lane >> 4)*16);
    const float* Wwarp = W + (size_t)(nblk + w*16)*K;

    auto loadA = [&](int s, int b){
        #pragma unroll
        for (int i = 0; i < 4; i++){
            int p = tid + i*256;
            int row = p >> 4, c16 = p & 15;
            cp16(sraw + b*17408 + row*272 + c16*16, A + (size_t)row*K + kbeg + s*128 + c16*8);
        }
    };
    auto issueW = [&](int g, int st){
        int kco = kbeg + g*32;
        char* wd = sraw + 34816 + w*5120 + st*2560;
        #pragma unroll
        for (int j = 0; j < 4; j++){
            int q = lane + j*32;
            int row = q >> 3, c8 = q & 7;
            cp16(wd + row*160 + c8*16, Wwarp + (size_t)row*K + kco + c8*4);
        }
    };

    float acc[4][2][4];
    #pragma unroll
    for (int i=0;i<4;i++)
        #pragma unroll
        for (int j=0;j<2;j++)
            #pragma unroll
            for (int q=0;q<4;q++) acc[i][j][q] = 0.f;

    loadA(0, 0);
    issueW(0, 0);
    asm volatile("cp.async.commit_group;");
    issueW(1, 1);
    asm volatile("cp.async.commit_group;");

    for (int g = 0; g < nchunk; g++){
        if (g == nchunk - 1) asm volatile("cp.async.wait_group 0;");
        else                 asm volatile("cp.async.wait_group 1;");
        __syncwarp();
        if ((g & 3) == 0) __syncthreads();

        {
            int bufA = (g >> 2) & 1;
            uint32_t aHb = sb + bufA*17408 + aoff + (uint32_t)((g & 3) * 64);
            const float2* wst = (const float2*)(sraw + 34816 + w*5120 + (g & 1)*2560);

            #pragma unroll
            for (int ki = 0; ki < 2; ki++){
                uint32_t bh[2][2];
                #pragma unroll
                for (int nt = 0; nt < 2; nt++){
                    int nl = nt*8 + r;
                    const float2* wp = wst + nl*20 + ki*8 + c;
                    float2 w0 = wp[0], w1 = wp[4];
                    bh[nt][0] = h2_pack(w0.x, w0.y);
                    bh[nt][1] = h2_pack(w1.x, w1.y);
                }
                #pragma unroll
                for (int mt = 0; mt < 4; mt++){
                    uint32_t ah[4];
                    ldsm4(ah, aHb + mt*4352 + ki*32);
                    mma16816h(acc[mt][0], ah, bh[0][0], bh[0][1]);
                    mma16816h(acc[mt][1], ah, bh[1][0], bh[1][1]);
                }
            }
        }

        bool did = false;
        if ((g & 3) == 0 && (g >> 2) + 1 < nsec){
            loadA((g >> 2) + 1, ((g >> 2) + 1) & 1);
            did = true;
        }
        if (g + 2 < nchunk){
            issueW(g + 2, (g + 2) & 1);
            did = true;
        }
        if (did) asm volatile("cp.async.commit_group;");
    }

    int nw = nblk + w*16, cq = c*2;
    if (mode == 0){
        float* o = outp + (size_t)(zz*64) * N;
        #pragma unroll
        for (int mt = 0; mt < 4; mt++)
            #pragma unroll
            for (int nt = 0; nt < 2; nt++){
                int row = mt*16 + r, col = nw + nt*8 + cq;
                *(float2*)(o + (size_t)row*N + col)     = make_float2(acc[mt][nt][0], acc[mt][nt][1]);
                *(float2*)(o + (size_t)(row+8)*N + col) = make_float2(acc[mt][nt][2], acc[mt][nt][3]);
            }
    } else {
        #pragma unroll
        for (int mt = 0; mt < 4; mt++)
            #pragma unroll
            for (int nt = 0; nt < 2; nt++){
                int row = mt*16 + r, col = nw + nt*8 + cq;
                float2 bb = *(const float2*)(bias + col);
                *(float2*)(outp + (size_t)row*N + col)     = make_float2(acc[mt][nt][0] + bb.x, acc[mt][nt][1] + bb.y);
                *(float2*)(outp + (size_t)(row+8)*N + col) = make_float2(acc[mt][nt][2] + bb.x, acc[mt][nt][3] + bb.y);
            }
    }
}

// ---------------- GRU elementwise cell (8 split-K partials) ----------------
__global__ void gru_cell_k(const float* __restrict__ bi, const float* __restrict__ bh,
                           const float* __restrict__ hprev, float* __restrict__ hout,
                           int layer)
{
    int idx = blockIdx.x*256 + threadIdx.x;   // 65536
    int b = idx >> 10, j = idx & 1023;
    float xr=0.f, xz=0.f, xn=0.f, hr=0.f, hz=0.f, hn=0.f;
    #pragma unroll
    for (int ks = 0; ks < 8; ks++){
        const float* gi = g_gpart + (size_t)(ks*64 + b)*G3;
        const float* gh = g_gpart + (size_t)((8+ks)*64 + b)*G3;
        xr += gi[j]; xz += gi[1024+j]; xn += gi[2048+j];
        hr += gh[j]; hz += gh[1024+j]; hn += gh[2048+j];
    }
    xr += bi[j]; xz += bi[1024+j]; xn += bi[2048+j];
    hr += bh[j]; hz += bh[1024+j]; hn += bh[2048+j];
    float rr = 1.f/(1.f + expf(-(xr+hr)));
    float zg = 1.f/(1.f + expf(-(xz+hz)));
    float nn = tanhf(xn + rr*hn);
    float h  = (1.f - zg)*nn + zg*hprev[idx];
    hout[idx] = h;
    if (layer == 0){
        __nv_bfloat16 hi, lo; split1(h, &hi, &lo);
        g_h0hi[idx] = hi; g_h0lo[idx] = lo;
    } else {
        g_cat16[b*2048 + j] = __float2half_rn(h);
        g_h1[idx] = h;
    }
}

// ---------------- attention pass 1: cp.async row double-buffer, online softmax ----------------
#define ASMEM 69760
__global__ void __launch_bounds__(256, 2) attn_pass_k(const float* __restrict__ enc)
{
    extern __shared__ char araw[];
    float* sbuf = (float*)araw;                 // [8 warps][2][1024]
    float* cbuf = sbuf;                         // alias after main loop
    float* smhv = (float*)(araw + 65536);       // [1024]
    float* sm_m = smhv + 1024;
    float* sm_s = sm_m + 8;

    int b = blockIdx.x >> 4, cch = blockIdx.x & 15;
    int tid = threadIdx.x, w = tid >> 5, lane = tid & 31;

    for (int i = tid; i < 1024; i += 256) smhv[i] = g_h1[b*1024 + i];
    __syncthreads();
    float4 hv[8];
    #pragma unroll
    for (int k = 0; k < 8; k++) hv[k] = ((const float4*)smhv)[lane + 32*k];
    float4 ctx[8];
    #pragma unroll
    for (int k = 0; k < 8; k++) ctx[k] = make_float4(0.f,0.f,0.f,0.f);
    float m = -1e30f, ssum = 0.f;

    const float* ebase = enc + ((size_t)b*LSEQ + cch*128 + w*16)*1024;
    float* mybuf = sbuf + w*2048;

    #pragma unroll
    for (int s = 0; s < 8; s++)
        cp16(mybuf + lane*4 + s*128, ebase + lane*4 + s*128);
    asm volatile("cp.async.commit_group;");

    for (int i = 0; i < 16; i++){
        if (i < 15){
            const float* src = ebase + (size_t)(i+1)*1024;
            float* dst = mybuf + ((i+1)&1)*1024;
            #pragma unroll
            for (int s = 0; s < 8; s++)
                cp16(dst + lane*4 + s*128, src + lane*4 + s*128);
            asm volatile("cp.async.commit_group;");
            asm volatile("cp.async.wait_group 1;");
        } else {
            asm volatile("cp.async.wait_group 0;");
        }
        const float4* v4 = (const float4*)(mybuf + (i&1)*1024);
        float4 v[8];
        #pragma unroll
        for (int k = 0; k < 8; k++) v[k] = v4[lane + 32*k];
        float d = 0.f;
        #pragma unroll
        for (int k = 0; k < 8; k++){
            d = fmaf(v[k].x, hv[k].x, d); d = fmaf(v[k].y, hv[k].y, d);
            d = fmaf(v[k].z, hv[k].z, d); d = fmaf(v[k].w, hv[k].w, d);
        }
        #pragma unroll
        for (int off = 16; off; off >>= 1) d += __shfl_xor_sync(0xffffffffu, d, off);
        if (lane == 0) g_scores[b*LSEQ + cch*128 + w*16 + i] = d;
        if (d > m){
            float sc = __expf(m - d);
            ssum *= sc;
            #pragma unroll
            for (int k = 0; k < 8; k++){
                ctx[k].x *= sc; ctx[k].y *= sc; ctx[k].z *= sc; ctx[k].w *= sc;
            }
            m = d;
        }
        float wg = __expf(d - m);
        ssum += wg;
        #pragma unroll
        for (int k = 0; k < 8; k++){
            ctx[k].x = fmaf(wg, v[k].x, ctx[k].x); ctx[k].y = fmaf(wg, v[k].y, ctx[k].y);
            ctx[k].z = fmaf(wg, v[k].z, ctx[k].z); ctx[k].w = fmaf(wg, v[k].w, ctx[k].w);
        }
    }

    if (lane == 0){ sm_m[w] = m; sm_s[w] = ssum; }
    __syncthreads();
    float mb = sm_m[0];
    #pragma unroll
    for (int jw = 1; jw < 8; jw++) mb = fmaxf(mb, sm_m[jw]);
    float sc = __expf(m - mb);
    #pragma unroll
    for (int k = 0; k < 8; k++){
        int e2 = (lane + 32*k)*4;
        cbuf[w*1024 + e2+0] = ctx[k].x*sc; cbuf[w*1024 + e2+1] = ctx[k].y*sc;
        cbuf[w*1024 + e2+2] = ctx[k].z*sc; cbuf[w*1024 + e2+3] = ctx[k].w*sc;
    }
    __syncthreads();
    for (int e2 = tid; e2 < 1024; e2 += 256){
        float s = 0.f;
        #pragma unroll
        for (int jw = 0; jw < 8; jw++) s += cbuf[jw*1024 + e2];
        g_pctx[(size_t)(b*16 + cch)*1024 + e2] = s;
    }
    if (tid == 0){
        float zb = 0.f;
        #pragma unroll
        for (int jw = 0; jw < 8; jw++) zb += sm_s[jw]*__expf(sm_m[jw] - mb);
        g_pm[b*16 + cch] = mb; g_ps[b*16 + cch] = zb;
    }
}

// ---------------- attention finalize ----------------
__global__ void attn_fin_k(float* __restrict__ out_attn)
{
    int b = blockIdx.x, tid = threadIdx.x;
    float M = -1e30f;
    #pragma unroll
    for (int cc = 0; cc < 16; cc++) M = fmaxf(M, g_pm[b*16 + cc]);
    float Z = 0.f;
    #pragma unroll
    for (int cc = 0; cc < 16; cc++) Z += g_ps[b*16 + cc]*__expf(g_pm[b*16 + cc] - M);
    float inv = 1.f / Z;
    for (int l = tid; l < LSEQ; l += 256)
        out_attn[b*LSEQ + l] = __expf(g_scores[b*LSEQ + l] - M) * inv;
    for (int e = tid; e < 1024; e += 256){
        float s = 0.f;
        #pragma unroll
        for (int cc = 0; cc < 16; cc++)
            s += __expf(g_pm[b*16 + cc] - M) * g_pctx[(size_t)(b*16 + cc)*1024 + e];
        g_cat16[b*2048 + 1024 + e] = __float2half_rn(s * inv);
    }
}

// ---------------- Wc combine: 16 partials + bias + tanh -> fp16 cc ----------------
__global__ void cc_comb_k(const float* __restrict__ bc)
{
    int idx = blockIdx.x*256 + threadIdx.x;  // 65536
    int b = idx >> 10, n = idx & 1023;
    float s = bc[n];
    #pragma unroll
    for (int z = 0; z < 16; z++) s += g_ccpart[(size_t)(z*64 + b)*1024 + n];
    g_cc16[idx] = __float2half_rn(tanhf(s));
}

// ---------------- launch ----------------
extern "C" void kernel_launch(void* const* d_in, const int* in_sizes, int n_in,
                              void* d_out, int out_size)
{
    const int*   seq  = (const int*)d_in[0];
    const float* lh   = (const float*)d_in[1];
    const float* enc  = (const float*)d_in[2];
    const float* emb  = (const float*)d_in[3];
    const float* Wih0 = (const float*)d_in[4];
    const float* Whh0 = (const float*)d_in[5];
    const float* bih0 = (const float*)d_in[6];
    const float* bhh0 = (const float*)d_in[7];
    const float* Wih1 = (const float*)d_in[8];
    const float* Whh1 = (const float*)d_in[9];
    const float* bih1 = (const float*)d_in[10];
    const float* bhh1 = (const float*)d_in[11];
    const float* Wc   = (const float*)d_in[12];
    const float* bc   = (const float*)d_in[13];
    const float* Wout = (const float*)d_in[14];
    const float* bout = (const float*)d_in[15];

    float* out        = (float*)d_out;
    float* out_logits = out;                                   // [64, 32000]
    float* out_hidden = out + (size_t)BATCH*NVOC;              // [2, 64, 1024]
    float* out_attn   = out_hidden + 2*BATCH*HDIM;             // [64, 1, 2048]

    cudaFuncSetAttribute(gemm3_k, cudaFuncAttributeMaxDynamicSharedMemorySize, GSMEM3);
    cudaFuncSetAttribute(gemm16_k, cudaFuncAttributeMaxDynamicSharedMemorySize, WSMEM);
    cudaFuncSetAttribute(attn_pass_k, cudaFuncAttributeMaxDynamicSharedMemorySize, ASMEM);

    float* ccpart_ptr; cudaGetSymbolAddress((void**)&ccpart_ptr, g_ccpart);
    __half* cat16_ptr; cudaGetSymbolAddress((void**)&cat16_ptr, g_cat16);
    __half* cc16_ptr;  cudaGetSymbolAddress((void**)&cc16_ptr,  g_cc16);

    prep_k<<<768, 256>>>(seq, emb, lh);

    gemm3_k<<<dim3(24, 2, 8), 256, GSMEM3>>>(Wih0, Whh0, 1024, G3, 128, 0);
    gru_cell_k<<<256, 256>>>(bih0, bhh0, lh, out_hidden, 0);

    gemm3_k<<<dim3(24, 2, 8), 256, GSMEM3>>>(Wih1, Whh1, 1024, G3, 128, 1);
    gru_cell_k<<<256, 256>>>(bih1, bhh1, lh + BATCH*HDIM, out_hidden + BATCH*HDIM, 1);

    attn_pass_k<<<1024, 256, ASMEM>>>(enc);
    attn_fin_k<<<64, 256>>>(out_attn);

    gemm16_k<<<dim3(8, 1, 16), 256, WSMEM>>>(cat16_ptr, Wc, nullptr, ccpart_ptr, 2048, 1024, 128, 0);
    cc_comb_k<<<256, 256>>>(bc);

    gemm16_k<<<dim3(250, 1, 1), 256, WSMEM>>>(cc16_ptr, Wout, bout, out_logits, 1024, NVOC, 1024, 1);
}

// round 13
// speedup vs baseline: 1.2024x; 1.0230x over previous
#include <cuda_runtime.h>
#include <cuda_bf16.h>
#include <cuda_fp16.h>
#include <cstdint>

#define BATCH 64
#define HDIM  1024
#define LSEQ  2048
#define NVOC  32000
#define G3    3072

#define PDL_TRIGGER asm volatile("griddepcontrol.launch_dependents;" ::: "memory")
#define PDL_WAIT    asm volatile("griddepcontrol.wait;" ::: "memory")

// ---------------- scratch (device globals; no allocation) ----------------
__device__ __nv_bfloat16 g_xhi[BATCH*HDIM],  g_xlo[BATCH*HDIM];
__device__ __nv_bfloat16 g_hphi[2*BATCH*HDIM], g_hplo[2*BATCH*HDIM];
__device__ __nv_bfloat16 g_h0hi[BATCH*HDIM], g_h0lo[BATCH*HDIM];
__device__ float         g_gpart[16*BATCH*G3];    // [y*8+z][64][3072]
__device__ float         g_h1[BATCH*HDIM];
__device__ __half        g_cat16[BATCH*2*HDIM];
__device__ float         g_scores[BATCH*LSEQ];
__device__ float         g_pm[BATCH*16], g_ps[BATCH*16];
__device__ float         g_pctx[BATCH*16*HDIM];
__device__ float         g_ccpart[16*BATCH*HDIM]; // [z][64][1024]
__device__ __half        g_cc16[BATCH*HDIM];

// ---------------- helpers ----------------
__device__ __forceinline__ uint32_t pk_hi(float x, float y){
    return (__float_as_uint(x) >> 16) | (__float_as_uint(y) & 0xffff0000u);
}
__device__ __forceinline__ uint32_t pk_lo(float x, float y){
    float rx = x - __uint_as_float(__float_as_uint(x) & 0xffff0000u);
    float ry = y - __uint_as_float(__float_as_uint(y) & 0xffff0000u);
    return (__float_as_uint(rx) >> 16) | (__float_as_uint(ry) & 0xffff0000u);
}
__device__ __forceinline__ void split1(float v, __nv_bfloat16* hi, __nv_bfloat16* lo){
    uint32_t u  = __float_as_uint(v);
    uint32_t uh = u & 0xffff0000u;
    float r = v - __uint_as_float(uh);
    *hi = __ushort_as_bfloat16((unsigned short)(uh >> 16));
    *lo = __ushort_as_bfloat16((unsigned short)(__float_as_uint(r) >> 16));
}
__device__ __forceinline__ void mma16816(float* c, const uint32_t* a, uint32_t b0, uint32_t b1){
    asm volatile("mma.sync.aligned.m16n8k16.row.col.f32.bf16.bf16.f32 "
        "{%0,%1,%2,%3}, {%4,%5,%6,%7}, {%8,%9}, {%0,%1,%2,%3};"
        : "+f"(c[0]), "+f"(c[1]), "+f"(c[2]), "+f"(c[3])
        : "r"(a[0]), "r"(a[1]), "r"(a[2]), "r"(a[3]), "r"(b0), "r"(b1));
}
__device__ __forceinline__ void mma16816h(float* c, const uint32_t* a, uint32_t b0, uint32_t b1){
    asm volatile("mma.sync.aligned.m16n8k16.row.col.f32.f16.f16.f32 "
        "{%0,%1,%2,%3}, {%4,%5,%6,%7}, {%8,%9}, {%0,%1,%2,%3};"
        : "+f"(c[0]), "+f"(c[1]), "+f"(c[2]), "+f"(c[3])
        : "r"(a[0]), "r"(a[1]), "r"(a[2]), "r"(a[3]), "r"(b0), "r"(b1));
}
__device__ __forceinline__ void ldsm4(uint32_t* d, uint32_t saddr){
    asm volatile("ldmatrix.sync.aligned.m8n8.x4.shared.b16 {%0,%1,%2,%3}, [%4];"
        : "=r"(d[0]), "=r"(d[1]), "=r"(d[2]), "=r"(d[3]) : "r"(saddr));
}
__device__ __forceinline__ void cp16(void* sdst, const void* gsrc){
    uint32_t s = (uint32_t)__cvta_generic_to_shared(sdst);
    asm volatile("cp.async.cg.shared.global [%0], [%1], 16;" :: "r"(s), "l"(gsrc));
}
__device__ __forceinline__ uint32_t h2_pack(float x, float y){
    uint32_t u;
    asm("cvt.rn.f16x2.f32 %0, %1, %2;" : "=r"(u) : "f"(y), "f"(x));  // y->hi, x->lo
    return u;
}

// ---------------- prep: embed gather + hi/lo split of x and h_prev ----------------
__global__ void prep_k(const int* __restrict__ seq, const float* __restrict__ embed,
                       const float* __restrict__ lh)
{
    PDL_TRIGGER;
    PDL_WAIT;
    int idx = blockIdx.x*256 + threadIdx.x;     // 3 * 65536
    int z = idx >> 16, r = idx & 65535;
    float v;
    if (z == 0){
        int b = r >> 10, j = r & 1023;
        v = embed[(size_t)seq[b]*HDIM + j];
    } else {
        v = lh[(size_t)(z-1)*BATCH*HDIM + r];
    }
    __nv_bfloat16 hi, lo; split1(v, &hi, &lo);
    if (z == 0){ g_xhi[r] = hi; g_xlo[r] = lo; }
    else       { g_hphi[(z-1)*BATCH*HDIM + r] = hi; g_hplo[(z-1)*BATCH*HDIM + r] = lo; }
}

// ---------------- gemm3: bf16 3-term split (GRU) ----------------
// partial = act(64xK) @ W(NxK)^T over K-range [zz*KS, (zz+1)*KS)  -> g_gpart[y*gridDim.z+zz]
// Prologue: W chunk 0,1 prefetched BEFORE griddepcontrol.wait (weights are inputs).
#define GSMEM3 110592
__global__ void __launch_bounds__(256, 2)
gemm3_k(const float* __restrict__ W0, const float* __restrict__ W1,
        int K, int N, int KS, int mode)
{
    extern __shared__ char sraw[];
    uint32_t sb = (uint32_t)__cvta_generic_to_shared(sraw);

    PDL_TRIGGER;

    int y = blockIdx.y, zz = blockIdx.z;
    const float* W = y ? W1 : W0;
    const __nv_bfloat16 *Ahp, *Alp;
    if (mode == 0){ Ahp = y ? g_hphi : g_xhi;  Alp = y ? g_hplo : g_xlo; }
    else {
        Ahp = y ? (g_hphi + BATCH*HDIM) : g_h0hi;
        Alp = y ? (g_hplo + BATCH*HDIM) : g_h0lo;
    }
    float* op = g_gpart;
    const uint32_t* Agh = (const uint32_t*)Ahp;
    const uint32_t* Agl = (const uint32_t*)Alp;

    int tid = threadIdx.x, w = tid >> 5, lane = tid & 31;
    int r = lane >> 2, c = lane & 3;
    int nblk = blockIdx.x * 128;
    int K2 = K >> 1;
    int kbeg = zz * KS;
    int nchunk = KS >> 5;
    int nsec = KS >> 7;

    uint32_t aoff = (uint32_t)((lane & 15)*272 + (lane >> 4)*16);
    const float* Wwarp = W + (size_t)(nblk + w*16)*K;

    auto loadA = [&](int s, int b){
        int ku = (kbeg + s*128) >> 1;
        #pragma unroll
        for (int i = 0; i < 4; i++){
            int p = tid + i*256;
            int row = p >> 4, c16 = p & 15;
            const uint32_t* sh = Agh + (size_t)row*K2 + ku + c16*4;
            const uint32_t* sl = Agl + (size_t)row*K2 + ku + c16*4;
            cp16(sraw + b*34816 + row*272 + c16*16, sh);
            cp16(sraw + b*34816 + 17408 + row*272 + c16*16, sl);
        }
    };
    auto issueW = [&](int g, int st){
        int kco = kbeg + g*32;
        char* wd = sraw + 69632 + w*5120 + st*2560;
        #pragma unroll
        for (int j = 0; j < 4; j++){
            int q = lane + j*32;
            int row = q >> 3, c8 = q & 7;
            cp16(wd + row*160 + c8*16, Wwarp + (size_t)row*K + kco + c8*4);
        }
    };

    float acc[4][2][4];
    #pragma unroll
    for (int i=0;i<4;i++)
        #pragma unroll
        for (int j=0;j<2;j++)
            #pragma unroll
            for (int q=0;q<4;q++) acc[i][j][q] = 0.f;

    // weight prefetch BEFORE dependency wait
    issueW(0, 0);
    asm volatile("cp.async.commit_group;");     // G0
    issueW(1, 1);
    asm volatile("cp.async.commit_group;");     // G1

    PDL_WAIT;                                   // activations now valid

    loadA(0, 0);
    asm volatile("cp.async.commit_group;");     // G2

    for (int g = 0; g < nchunk; g++){
        if (g == 0 || g == nchunk - 1) asm volatile("cp.async.wait_group 0;");
        else                           asm volatile("cp.async.wait_group 1;");
        __syncwarp();
        if ((g & 3) == 0) __syncthreads();

        {
            int bufA = (g >> 2) & 1;
            uint32_t cloc = (uint32_t)((g & 3) * 64);
            uint32_t aHb = sb + bufA*34816 + aoff + cloc;
            uint32_t aLb = aHb + 17408;
            const float2* wst = (const float2*)(sraw + 69632 + w*5120 + (g & 1)*2560);

            #pragma unroll
            for (int ki = 0; ki < 2; ki++){
                uint32_t bh[2][2], bl[2][2];
                #pragma unroll
                for (int nt = 0; nt < 2; nt++){
                    int nl = nt*8 + r;
                    const float2* wp = wst + nl*20 + ki*8 + c;
                    float2 w0 = wp[0], w1 = wp[4];
                    bh[nt][0] = pk_hi(w0.x, w0.y);  bl[nt][0] = pk_lo(w0.x, w0.y);
                    bh[nt][1] = pk_hi(w1.x, w1.y);  bl[nt][1] = pk_lo(w1.x, w1.y);
                }
                #pragma unroll
                for (int mt = 0; mt < 4; mt++){
                    uint32_t ah[4], aw[4];
                    ldsm4(ah, aHb + mt*4352 + ki*32);
                    ldsm4(aw, aLb + mt*4352 + ki*32);
                    #pragma unroll
                    for (int nt = 0; nt < 2; nt++){
                        mma16816(acc[mt][nt], ah, bh[nt][0], bh[nt][1]);
                        mma16816(acc[mt][nt], aw, bh[nt][0], bh[nt][1]);
                        mma16816(acc[mt][nt], ah, bl[nt][0], bl[nt][1]);
                    }
                }
            }
        }

        bool did = false;
        if ((g & 3) == 0 && (g >> 2) + 1 < nsec){
            loadA((g >> 2) + 1, ((g >> 2) + 1) & 1);
            did = true;
        }
        if (g + 2 < nchunk){
            issueW(g + 2, (g + 2) & 1);
            did = true;
        }
        if (did) asm volatile("cp.async.commit_group;");
    }

    int nw = nblk + w*16, cq = c*2;
    float* o = op + (size_t)((y*gridDim.z + zz) * 64) * N;
    #pragma unroll
    for (int mt = 0; mt < 4; mt++)
        #pragma unroll
        for (int nt = 0; nt < 2; nt++){
            int row = mt*16 + r, col = nw + nt*8 + cq;
            *(float2*)(o + (size_t)row*N + col)     = make_float2(acc[mt][nt][0], acc[mt][nt][1]);
            *(float2*)(o + (size_t)(row+8)*N + col) = make_float2(acc[mt][nt][2], acc[mt][nt][3]);
        }
}

// ---------------- gemm16: single-term fp16 GEMM (Wc partials + Wout direct) ----------------
// mode 0: partial -> outp[(zz*64+row)*N]   mode 1: direct + bias -> outp[row*N]
#define WSMEM 75776
__global__ void __launch_bounds__(256, 2)
gemm16_k(const __half* __restrict__ A, const float* __restrict__ W,
         const float* __restrict__ bias, float* __restrict__ outp,
         int K, int N, int KS, int mode)
{
    extern __shared__ char sraw[];
    uint32_t sb = (uint32_t)__cvta_generic_to_shared(sraw);

    PDL_TRIGGER;

    int tid = threadIdx.x, w = tid >> 5, lane = tid & 31;
    int r = lane >> 2, c = lane & 3;
    int nblk = blockIdx.x * 128;
    int zz = blockIdx.z;
    int kbeg = zz * KS;
    int nchunk = KS >> 5;
    int nsec = KS >> 7;

    uint32_t aoff = (uint32_t)((lane & 15)*272 + (lane >> 4)*16);
    const float* Wwarp = W + (size_t)(nblk + w*16)*K;

    auto loadA = [&](int s, int b){
        #pragma unroll
        for (int i = 0; i < 4; i++){
            int p = tid + i*256;
            int row = p >> 4, c16 = p & 15;
            cp16(sraw + b*17408 + row*272 + c16*16, A + (size_t)row*K + kbeg + s*128 + c16*8);
        }
    };
    auto issueW = [&](int g, int st){
        int kco = kbeg + g*32;
        char* wd = sraw + 34816 + w*5120 + st*2560;
        #pragma unroll
        for (int j = 0; j < 4; j++){
            int q = lane + j*32;
            int row = q >> 3, c8 = q & 7;
            cp16(wd + row*160 + c8*16, Wwarp + (size_t)row*K + kco + c8*4);
        }
    };

    float acc[4][2][4];
    #pragma unroll
    for (int i=0;i<4;i++)
        #pragma unroll
        for (int j=0;j<2;j++)
            #pragma unroll
            for (int q=0;q<4;q++) acc[i][j][q] = 0.f;

    // weight prefetch BEFORE dependency wait
    issueW(0, 0);
    asm volatile("cp.async.commit_group;");     // G0
    issueW(1, 1);
    asm volatile("cp.async.commit_group;");     // G1

    PDL_WAIT;                                   // A (cat16/cc16) now valid

    loadA(0, 0);
    asm volatile("cp.async.commit_group;");     // G2

    for (int g = 0; g < nchunk; g++){
        if (g == 0 || g == nchunk - 1) asm volatile("cp.async.wait_group 0;");
        else                           asm volatile("cp.async.wait_group 1;");
        __syncwarp();
        if ((g & 3) == 0) __syncthreads();

        {
            int bufA = (g >> 2) & 1;
            uint32_t aHb = sb + bufA*17408 + aoff + (uint32_t)((g & 3) * 64);
            const float2* wst = (const float2*)(sraw + 34816 + w*5120 + (g & 1)*2560);

            #pragma unroll
            for (int ki = 0; ki < 2; ki++){
                uint32_t bh[2][2];
                #pragma unroll
                for (int nt = 0; nt < 2; nt++){
                    int nl = nt*8 + r;
                    const float2* wp = wst + nl*20 + ki*8 + c;
                    float2 w0 = wp[0], w1 = wp[4];
                    bh[nt][0] = h2_pack(w0.x, w0.y);
                    bh[nt][1] = h2_pack(w1.x, w1.y);
                }
                #pragma unroll
                for (int mt = 0; mt < 4; mt++){
                    uint32_t ah[4];
                    ldsm4(ah, aHb + mt*4352 + ki*32);
                    mma16816h(acc[mt][0], ah, bh[0][0], bh[0][1]);
                    mma16816h(acc[mt][1], ah, bh[1][0], bh[1][1]);
                }
            }
        }

        bool did = false;
        if ((g & 3) == 0 && (g >> 2) + 1 < nsec){
            loadA((g >> 2) + 1, ((g >> 2) + 1) & 1);
            did = true;
        }
        if (g + 2 < nchunk){
            issueW(g + 2, (g + 2) & 1);
            did = true;
        }
        if (did) asm volatile("cp.async.commit_group;");
    }

    int nw = nblk + w*16, cq = c*2;
    if (mode == 0){
        float* o = outp + (size_t)(zz*64) * N;
        #pragma unroll
        for (int mt = 0; mt < 4; mt++)
            #pragma unroll
            for (int nt = 0; nt < 2; nt++){
                int row = mt*16 + r, col = nw + nt*8 + cq;
                *(float2*)(o + (size_t)row*N + col)     = make_float2(acc[mt][nt][0], acc[mt][nt][1]);
                *(float2*)(o + (size_t)(row+8)*N + col) = make_float2(acc[mt][nt][2], acc[mt][nt][3]);
            }
    } else {
        #pragma unroll
        for (int mt = 0; mt < 4; mt++)
            #pragma unroll
            for (int nt = 0; nt < 2; nt++){
                int row = mt*16 + r, col = nw + nt*8 + cq;
                float2 bb = *(const float2*)(bias + col);
                *(float2*)(outp + (size_t)row*N + col)     = make_float2(acc[mt][nt][0] + bb.x, acc[mt][nt][1] + bb.y);
                *(float2*)(outp + (size_t)(row+8)*N + col) = make_float2(acc[mt][nt][2] + bb.x, acc[mt][nt][3] + bb.y);
            }
    }
}

// ---------------- GRU elementwise cell (8 split-K partials) ----------------
__global__ void gru_cell_k(const float* __restrict__ bi, const float* __restrict__ bh,
                           const float* __restrict__ hprev, float* __restrict__ hout,
                           int layer)
{
    PDL_TRIGGER;
    PDL_WAIT;
    int idx = blockIdx.x*256 + threadIdx.x;   // 65536
    int b = idx >> 10, j = idx & 1023;
    float xr=0.f, xz=0.f, xn=0.f, hr=0.f, hz=0.f, hn=0.f;
    #pragma unroll
    for (int ks = 0; ks < 8; ks++){
        const float* gi = g_gpart + (size_t)(ks*64 + b)*G3;
        const float* gh = g_gpart + (size_t)((8+ks)*64 + b)*G3;
        xr += gi[j]; xz += gi[1024+j]; xn += gi[2048+j];
        hr += gh[j]; hz += gh[1024+j]; hn += gh[2048+j];
    }
    xr += bi[j]; xz += bi[1024+j]; xn += bi[2048+j];
    hr += bh[j]; hz += bh[1024+j]; hn += bh[2048+j];
    float rr = 1.f/(1.f + expf(-(xr+hr)));
    float zg = 1.f/(1.f + expf(-(xz+hz)));
    float nn = tanhf(xn + rr*hn);
    float h  = (1.f - zg)*nn + zg*hprev[idx];
    hout[idx] = h;
    if (layer == 0){
        __nv_bfloat16 hi, lo; split1(h, &hi, &lo);
        g_h0hi[idx] = hi; g_h0lo[idx] = lo;
    } else {
        g_cat16[b*2048 + j] = __float2half_rn(h);
        g_h1[idx] = h;
    }
}

// ---------------- attention pass 1: cp.async row double-buffer, online softmax ----------------
#define ASMEM 69760
__global__ void __launch_bounds__(256, 2) attn_pass_k(const float* __restrict__ enc)
{
    extern __shared__ char araw[];
    float* sbuf = (float*)araw;                 // [8 warps][2][1024]
    float* cbuf = sbuf;                         // alias after main loop
    float* smhv = (float*)(araw + 65536);       // [1024]
    float* sm_m = smhv + 1024;
    float* sm_s = sm_m + 8;

    PDL_TRIGGER;

    int b = blockIdx.x >> 4, cch = blockIdx.x & 15;
    int tid = threadIdx.x, w = tid >> 5, lane = tid & 31;

    const float* ebase = enc + ((size_t)b*LSEQ + cch*128 + w*16)*1024;
    float* mybuf = sbuf + w*2048;

    // prefetch row 0 BEFORE dependency wait (enc is a pure input)
    #pragma unroll
    for (int s = 0; s < 8; s++)
        cp16(mybuf + lane*4 + s*128, ebase + lane*4 + s*128);
    asm volatile("cp.async.commit_group;");

    PDL_WAIT;                                   // g_h1 now valid

    for (int i = tid; i < 1024; i += 256) smhv[i] = g_h1[b*1024 + i];
    __syncthreads();
    float4 hv[8];
    #pragma unroll
    for (int k = 0; k < 8; k++) hv[k] = ((const float4*)smhv)[lane + 32*k];
    float4 ctx[8];
    #pragma unroll
    for (int k = 0; k < 8; k++) ctx[k] = make_float4(0.f,0.f,0.f,0.f);
    float m = -1e30f, ssum = 0.f;

    for (int i = 0; i < 16; i++){
        if (i < 15){
            const float* src = ebase + (size_t)(i+1)*1024;
            float* dst = mybuf + ((i+1)&1)*1024;
            #pragma unroll
            for (int s = 0; s < 8; s++)
                cp16(dst + lane*4 + s*128, src + lane*4 + s*128);
            asm volatile("cp.async.commit_group;");
            asm volatile("cp.async.wait_group 1;");
        } else {
            asm volatile("cp.async.wait_group 0;");
        }
        const float4* v4 = (const float4*)(mybuf + (i&1)*1024);
        float4 v[8];
        #pragma unroll
        for (int k = 0; k < 8; k++) v[k] = v4[lane + 32*k];
        float d = 0.f;
        #pragma unroll
        for (int k = 0; k < 8; k++){
            d = fmaf(v[k].x, hv[k].x, d); d = fmaf(v[k].y, hv[k].y, d);
            d = fmaf(v[k].z, hv[k].z, d); d = fmaf(v[k].w, hv[k].w, d);
        }
        #pragma unroll
        for (int off = 16; off; off >>= 1) d += __shfl_xor_sync(0xffffffffu, d, off);
        if (lane == 0) g_scores[b*LSEQ + cch*128 + w*16 + i] = d;
        if (d > m){
            float sc = __expf(m - d);
            ssum *= sc;
            #pragma unroll
            for (int k = 0; k < 8; k++){
                ctx[k].x *= sc; ctx[k].y *= sc; ctx[k].z *= sc; ctx[k].w *= sc;
            }
            m = d;
        }
        float wg = __expf(d - m);
        ssum += wg;
        #pragma unroll
        for (int k = 0; k < 8; k++){
            ctx[k].x = fmaf(wg, v[k].x, ctx[k].x); ctx[k].y = fmaf(wg, v[k].y, ctx[k].y);
            ctx[k].z = fmaf(wg, v[k].z, ctx[k].z); ctx[k].w = fmaf(wg, v[k].w, ctx[k].w);
        }
    }

    if (lane == 0){ sm_m[w] = m; sm_s[w] = ssum; }
    __syncthreads();
    float mb = sm_m[0];
    #pragma unroll
    for (int jw = 1; jw < 8; jw++) mb = fmaxf(mb, sm_m[jw]);
    float sc = __expf(m - mb);
    #pragma unroll
    for (int k = 0; k < 8; k++){
        int e2 = (lane + 32*k)*4;
        cbuf[w*1024 + e2+0] = ctx[k].x*sc; cbuf[w*1024 + e2+1] = ctx[k].y*sc;
        cbuf[w*1024 + e2+2] = ctx[k].z*sc; cbuf[w*1024 + e2+3] = ctx[k].w*sc;
    }
    __syncthreads();
    for (int e2 = tid; e2 < 1024; e2 += 256){
        float s = 0.f;
        #pragma unroll
        for (int jw = 0; jw < 8; jw++) s += cbuf[jw*1024 + e2];
        g_pctx[(size_t)(b*16 + cch)*1024 + e2] = s;
    }
    if (tid == 0){
        float zb = 0.f;
        #pragma unroll
        for (int jw = 0; jw < 8; jw++) zb += sm_s[jw]*__expf(sm_m[jw] - mb);
        g_pm[b*16 + cch] = mb; g_ps[b*16 + cch] = zb;
    }
}

// ---------------- attention finalize ----------------
__global__ void attn_fin_k(float* __restrict__ out_attn)
{
    PDL_TRIGGER;
    PDL_WAIT;
    int b = blockIdx.x, tid = threadIdx.x;
    float M = -1e30f;
    #pragma unroll
    for (int cc = 0; cc < 16; cc++) M = fmaxf(M, g_pm[b*16 + cc]);
    float Z = 0.f;
    #pragma unroll
    for (int cc = 0; cc < 16; cc++) Z += g_ps[b*16 + cc]*__expf(g_pm[b*16 + cc] - M);
    float inv = 1.f / Z;
    for (int l = tid; l < LSEQ; l += 256)
        out_attn[b*LSEQ + l] = __expf(g_scores[b*LSEQ + l] - M) * inv;
    for (int e = tid; e < 1024; e += 256){
        float s = 0.f;
        #pragma unroll
        for (int cc = 0; cc < 16; cc++)
            s += __expf(g_pm[b*16 + cc] - M) * g_pctx[(size_t)(b*16 + cc)*1024 + e];
        g_cat16[b*2048 + 1024 + e] = __float2half_rn(s * inv);
    }
}

// ---------------- Wc combine: 16 partials + bias + tanh -> fp16 cc ----------------
__global__ void cc_comb_k(const float* __restrict__ bc)
{
    PDL_TRIGGER;
    PDL_WAIT;
    int idx = blockIdx.x*256 + threadIdx.x;  // 65536
    int b = idx >> 10, n = idx & 1023;
    float s = bc[n];
    #pragma unroll
    for (int z = 0; z < 16; z++) s += g_ccpart[(size_t)(z*64 + b)*1024 + n];
    g_cc16[idx] = __float2half_rn(tanhf(s));
}

// ---------------- host: PDL launch helper ----------------
static inline void pdl_launch(const void* fn, dim3 gd, dim3 bd, size_t smem, void** args)
{
    cudaLaunchConfig_t cfg = {};
    cfg.gridDim = gd; cfg.blockDim = bd;
    cfg.dynamicSmemBytes = smem;
    cfg.stream = 0;
    cudaLaunchAttribute at[1];
    at[0].id = cudaLaunchAttributeProgrammaticStreamSerialization;
    at[0].val.programmaticStreamSerializationAllowed = 1;
    cfg.attrs = at; cfg.numAttrs = 1;
    cudaLaunchKernelExC(&cfg, fn, args);
}

// ---------------- launch ----------------
extern "C" void kernel_launch(void* const* d_in, const int* in_sizes, int n_in,
                              void* d_out, int out_size)
{
    const int*   seq  = (const int*)d_in[0];
    const float* lh   = (const float*)d_in[1];
    const float* enc  = (const float*)d_in[2];
    const float* emb  = (const float*)d_in[3];
    const float* Wih0 = (const float*)d_in[4];
    const float* Whh0 = (const float*)d_in[5];
    const float* bih0 = (const float*)d_in[6];
    const float* bhh0 = (const float*)d_in[7];
    const float* Wih1 = (const float*)d_in[8];
    const float* Whh1 = (const float*)d_in[9];
    const float* bih1 = (const float*)d_in[10];
    const float* bhh1 = (const float*)d_in[11];
    const float* Wc   = (const float*)d_in[12];
    const float* bc   = (const float*)d_in[13];
    const float* Wout = (const float*)d_in[14];
    const float* bout = (const float*)d_in[15];

    float* out        = (float*)d_out;
    float* out_logits = out;                                   // [64, 32000]
    float* out_hidden = out + (size_t)BATCH*NVOC;              // [2, 64, 1024]
    float* out_attn   = out_hidden + 2*BATCH*HDIM;             // [64, 1, 2048]

    cudaFuncSetAttribute(gemm3_k, cudaFuncAttributeMaxDynamicSharedMemorySize, GSMEM3);
    cudaFuncSetAttribute(gemm16_k, cudaFuncAttributeMaxDynamicSharedMemorySize, WSMEM);
    cudaFuncSetAttribute(attn_pass_k, cudaFuncAttributeMaxDynamicSharedMemorySize, ASMEM);

    float* ccpart_ptr; cudaGetSymbolAddress((void**)&ccpart_ptr, g_ccpart);
    __half* cat16_ptr; cudaGetSymbolAddress((void**)&cat16_ptr, g_cat16);
    __half* cc16_ptr;  cudaGetSymbolAddress((void**)&cc16_ptr,  g_cc16);

    int K1024 = 1024, K2048 = 2048;
    int Ng3 = G3, N1024 = 1024, Nvoc = NVOC;
    int KS128 = 128, KS1024 = 1024;
    int m0 = 0, m1 = 1;
    float* hid0 = out_hidden;
    float* hid1 = out_hidden + BATCH*HDIM;
    const float* lh0 = lh;
    const float* lh1 = lh + BATCH*HDIM;

    { void* a[] = {(void*)&seq, (void*)&emb, (void*)&lh};
      pdl_launch((const void*)prep_k, dim3(768), dim3(256), 0, a); }

    { void* a[] = {(void*)&Wih0, (void*)&Whh0, &K1024, &Ng3, &KS128, &m0};
      pdl_launch((const void*)gemm3_k, dim3(24, 2, 8), dim3(256), GSMEM3, a); }
    { void* a[] = {(void*)&bih0, (void*)&bhh0, (void*)&lh0, (void*)&hid0, &m0};
      pdl_launch((const void*)gru_cell_k, dim3(256), dim3(256), 0, a); }

    { void* a[] = {(void*)&Wih1, (void*)&Whh1, &K1024, &Ng3, &KS128, &m1};
      pdl_launch((const void*)gemm3_k, dim3(24, 2, 8), dim3(256), GSMEM3, a); }
    { void* a[] = {(void*)&bih1, (void*)&bhh1, (void*)&lh1, (void*)&hid1, &m1};
      pdl_launch((const void*)gru_cell_k, dim3(256), dim3(256), 0, a); }

    { void* a[] = {(void*)&enc};
      pdl_launch((const void*)attn_pass_k, dim3(1024), dim3(256), ASMEM, a); }
    { void* a[] = {(void*)&out_attn};
      pdl_launch((const void*)attn_fin_k, dim3(64), dim3(256), 0, a); }

    { void* a[] = {(void*)&cat16_ptr, (void*)&Wc, (void*)&bc, (void*)&ccpart_ptr, &K2048, &N1024, &KS128, &m0};
      pdl_launch((const void*)gemm16_k, dim3(8, 1, 16), dim3(256), WSMEM, a); }
    { void* a[] = {(void*)&bc};
      pdl_launch((const void*)cc_comb_k, dim3(256), dim3(256), 0, a); }

    { void* a[] = {(void*)&cc16_ptr, (void*)&Wout, (void*)&bout, (void*)&out_logits, &K1024, &Nvoc, &KS1024, &m1};
      pdl_launch((const void*)gemm16_k, dim3(250, 1, 1), dim3(256), WSMEM, a); }
}